// round 4
// baseline (speedup 1.0000x reference)
#include <cuda_runtime.h>
#include <cuda_fp16.h>

// ---------------- fixed problem capacities (dataset is fixed) ----------------
#define NMAX 100000
#define EMAX 3200000
#define HDIM 64
#define ODIM 32
#define FDIM 128
#define XSTR 65   // padded [k][n] stride: conflict-free stage-write and read

// ---------------- device scratch (no allocations allowed) ----------------
__device__ int   g_is32;                              // 1 if edge indices are int32
__device__ int   g_ecnt[NMAX];                        // in-degree (no self loop)
__device__ int   g_ptr[NMAX + 1];                     // CSR offsets
__device__ int   g_cursor[NMAX];                      // fill cursors
__device__ int   g_bsum[1024];                        // block sums for scan
__device__ float g_dinv[NMAX];                        // 1/sqrt(deg+1)
__device__ __align__(16) int     g_rows[EMAX];        // CSR adjacency: src per slot
__device__ __align__(16) __half2 g_s1h[NMAX * 32];    // fp16 dinv*(x@W1): 64 vals/node
__device__ __align__(16) __half  g_s2h[NMAX * ODIM];  // fp16 dinv*(z1@W2): 32 vals/node
__device__ __align__(16) float   g_z2[NMAX * ODIM];   // layer-2 output (fp32)

// fetch edge value j from a buffer that is either int32[2E] or int64[2E]
__device__ __forceinline__ int edge_at(const void* p, long long j, int is32) {
    if (is32) return ((const int*)p)[j];
    return (int)((const long long*)p)[j];
}

// ---------------- prep: dtype detect (block 0) + zero counters ----------------
__global__ void k_prep(const void* ei, int E, int N) {
    int i = blockIdx.x * blockDim.x + threadIdx.x;
    if (i < N) g_ecnt[i] = 0;
    if (blockIdx.x == 0) {
        __shared__ int bad;
        if (threadIdx.x == 0) bad = 0;
        __syncthreads();
        int n = (2 * E < 256) ? 2 * E : 256;
        if (threadIdx.x < n) {
            long long v = ((const long long*)ei)[threadIdx.x];
            if (v < 0 || v >= NMAX) atomicOr(&bad, 1);
        }
        __syncthreads();
        if (threadIdx.x == 0) g_is32 = bad;
    }
}

__global__ void k_count(const void* __restrict__ ei, int E) {
    int e = blockIdx.x * blockDim.x + threadIdx.x;
    if (e < E) {
        int c = edge_at(ei, (long long)E + e, g_is32);
        atomicAdd(&g_ecnt[c], 1);
    }
}

// block-local exclusive scan; partials to g_ptr, block totals to g_bsum
__global__ void k_scanA(int N) {
    __shared__ int sh[1024];
    int t = threadIdx.x;
    int i = blockIdx.x * 1024 + t;
    int v = (i < N) ? g_ecnt[i] : 0;
    sh[t] = v;
    __syncthreads();
    for (int off = 1; off < 1024; off <<= 1) {
        int y = 0;
        if (t >= off) y = sh[t - off];
        __syncthreads();
        sh[t] += y;
        __syncthreads();
    }
    if (i < N) g_ptr[i] = sh[t] - v;
    if (t == 1023) g_bsum[blockIdx.x] = sh[1023];
}

__global__ void k_scanB(int NB) {
    __shared__ int sh[1024];
    int t = threadIdx.x;
    int v = (t < NB) ? g_bsum[t] : 0;
    sh[t] = v;
    __syncthreads();
    for (int off = 1; off < 1024; off <<= 1) {
        int y = 0;
        if (t >= off) y = sh[t - off];
        __syncthreads();
        sh[t] += y;
        __syncthreads();
    }
    if (t < NB) g_bsum[t] = sh[t] - v;
}

__global__ void k_scanC(int N, int E) {
    int i = blockIdx.x * 1024 + threadIdx.x;
    if (i < N) {
        int p = g_ptr[i] + g_bsum[blockIdx.x];
        g_ptr[i] = p;
        g_cursor[i] = p;
        g_dinv[i] = rsqrtf((float)(g_ecnt[i] + 1));   // +1 self loop
    }
    if (i == 0) g_ptr[N] = E;
}

__global__ void k_fill(const void* __restrict__ ei, int E) {
    int e = blockIdx.x * blockDim.x + threadIdx.x;
    if (e < E) {
        int is32 = g_is32;
        int r = edge_at(ei, e, is32);
        int c = edge_at(ei, (long long)E + e, is32);
        int pos = atomicAdd(&g_cursor[c], 1);
        g_rows[pos] = r;
    }
}

// ---------------- GEMM1: s1h = fp16( dinv * (x @ W1) )   [N,128]x[128,64] ----------------
__global__ __launch_bounds__(256) void k_gemm1(const float* __restrict__ x,
                                               const float* __restrict__ W1, int N) {
    extern __shared__ float sm[];
    float* Ws = sm;                         // [128][64] row-major, 32KB
    float* xs = sm + FDIM * HDIM;           // [k][n] stride XSTR
    int t = threadIdx.x;
    for (int i = t; i < FDIM * HDIM; i += 256) Ws[i] = W1[i];

    int node0 = blockIdx.x * 64;
    int lane = t & 31, wrp = t >> 5;
#pragma unroll
    for (int rep = 0; rep < 32; rep++) {
        int n = wrp * 8 + (rep >> 2);
        int k = (rep & 3) * 32 + lane;
        int gn = node0 + n;
        float v = (gn < N) ? x[(size_t)gn * FDIM + k] : 0.f;
        xs[k * XSTR + n] = v;
    }
    __syncthreads();

    int n = t & 63;
    int og = t >> 6;
    float acc[16];
#pragma unroll
    for (int i = 0; i < 16; i++) acc[i] = 0.f;
    const float4* Ws4 = (const float4*)Ws;
#pragma unroll 4
    for (int k = 0; k < FDIM; k++) {
        float xv = xs[k * XSTR + n];
        float4 w0 = Ws4[k * 16 + og * 4 + 0];
        float4 w1 = Ws4[k * 16 + og * 4 + 1];
        float4 w2 = Ws4[k * 16 + og * 4 + 2];
        float4 w3 = Ws4[k * 16 + og * 4 + 3];
        acc[0]  = fmaf(xv, w0.x, acc[0]);  acc[1]  = fmaf(xv, w0.y, acc[1]);
        acc[2]  = fmaf(xv, w0.z, acc[2]);  acc[3]  = fmaf(xv, w0.w, acc[3]);
        acc[4]  = fmaf(xv, w1.x, acc[4]);  acc[5]  = fmaf(xv, w1.y, acc[5]);
        acc[6]  = fmaf(xv, w1.z, acc[6]);  acc[7]  = fmaf(xv, w1.w, acc[7]);
        acc[8]  = fmaf(xv, w2.x, acc[8]);  acc[9]  = fmaf(xv, w2.y, acc[9]);
        acc[10] = fmaf(xv, w2.z, acc[10]); acc[11] = fmaf(xv, w2.w, acc[11]);
        acc[12] = fmaf(xv, w3.x, acc[12]); acc[13] = fmaf(xv, w3.y, acc[13]);
        acc[14] = fmaf(xv, w3.z, acc[14]); acc[15] = fmaf(xv, w3.w, acc[15]);
    }
    int gn = node0 + n;
    if (gn < N) {
        float d = g_dinv[gn];
        unsigned int p[8];
#pragma unroll
        for (int j = 0; j < 8; j++) {
            __half2 h = __floats2half2_rn(d * acc[2 * j], d * acc[2 * j + 1]);
            p[j] = *(unsigned int*)&h;
        }
        uint4* dst = (uint4*)(g_s1h + (size_t)gn * 32 + og * 8);
        dst[0] = make_uint4(p[0], p[1], p[2], p[3]);
        dst[1] = make_uint4(p[4], p[5], p[6], p[7]);
    }
}

// ---- fused agg1 + gemm2: s2h = fp16( dinv * (relu(dinv*(sum+self)+b1) @ W2) ) ----
__global__ __launch_bounds__(256) void k_agg1g2(const float* __restrict__ b1,
                                                const float* __restrict__ W2, int N) {
    __shared__ float W2s[HDIM * ODIM];   // 8KB  [k][o]
    __shared__ float zsm[8][HDIM];       // 2KB  per-warp z1 row
    int t = threadIdx.x;
    for (int i = t; i < HDIM * ODIM; i += 256) W2s[i] = W2[i];
    __syncthreads();

    int w = blockIdx.x * 8 + (t >> 5);
    int lane = t & 31;
    int wl = t >> 5;
    if (w >= N) return;

    int beg = g_ptr[w], end = g_ptr[w + 1];
    float2 a = __half22float2(g_s1h[(size_t)w * 32 + lane]);   // self
    float ax = a.x, ay = a.y;
    int i = beg;
    for (; i + 8 <= end; i += 8) {
        int r0 = g_rows[i],     r1 = g_rows[i + 1], r2 = g_rows[i + 2], r3 = g_rows[i + 3];
        int r4 = g_rows[i + 4], r5 = g_rows[i + 5], r6 = g_rows[i + 6], r7 = g_rows[i + 7];
        float2 v0 = __half22float2(g_s1h[(size_t)r0 * 32 + lane]);
        float2 v1 = __half22float2(g_s1h[(size_t)r1 * 32 + lane]);
        float2 v2 = __half22float2(g_s1h[(size_t)r2 * 32 + lane]);
        float2 v3 = __half22float2(g_s1h[(size_t)r3 * 32 + lane]);
        float2 v4 = __half22float2(g_s1h[(size_t)r4 * 32 + lane]);
        float2 v5 = __half22float2(g_s1h[(size_t)r5 * 32 + lane]);
        float2 v6 = __half22float2(g_s1h[(size_t)r6 * 32 + lane]);
        float2 v7 = __half22float2(g_s1h[(size_t)r7 * 32 + lane]);
        ax += ((v0.x + v1.x) + (v2.x + v3.x)) + ((v4.x + v5.x) + (v6.x + v7.x));
        ay += ((v0.y + v1.y) + (v2.y + v3.y)) + ((v4.y + v5.y) + (v6.y + v7.y));
    }
    for (; i < end; i++) {
        float2 v = __half22float2(g_s1h[(size_t)g_rows[i] * 32 + lane]);
        ax += v.x; ay += v.y;
    }
    float d = g_dinv[w];
    float2 bb = ((const float2*)b1)[lane];
    float zx = fmaxf(fmaf(d, ax, bb.x), 0.f);
    float zy = fmaxf(fmaf(d, ay, bb.y), 0.f);
    zsm[wl][2 * lane]     = zx;
    zsm[wl][2 * lane + 1] = zy;
    __syncwarp();

    // per-lane output o = lane: s2[o] = d * sum_k z1[k] * W2[k][o]
    float a0 = 0.f, a1 = 0.f, a2 = 0.f, a3 = 0.f;
#pragma unroll
    for (int k = 0; k < HDIM; k += 4) {
        a0 = fmaf(zsm[wl][k],     W2s[k * 32 + lane],       a0);
        a1 = fmaf(zsm[wl][k + 1], W2s[(k + 1) * 32 + lane], a1);
        a2 = fmaf(zsm[wl][k + 2], W2s[(k + 2) * 32 + lane], a2);
        a3 = fmaf(zsm[wl][k + 3], W2s[(k + 3) * 32 + lane], a3);
    }
    float s = d * ((a0 + a1) + (a2 + a3));
    float s_hi = __shfl_down_sync(0xffffffffu, s, 1);
    if (!(lane & 1)) {
        ((__half2*)(g_s2h + (size_t)w * 32))[lane >> 1] = __floats2half2_rn(s, s_hi);
    }
}

// ---------------- agg2: z2 = dinv*(sum + self) + b2  (fp16 gather) ----------------
__global__ __launch_bounds__(256) void k_agg2(const float* __restrict__ b2, int N) {
    int w = (blockIdx.x * blockDim.x + threadIdx.x) >> 5;
    int lane = threadIdx.x & 31;
    if (w >= N) return;
    int beg = g_ptr[w], end = g_ptr[w + 1];
    float acc = __half2float(g_s2h[(size_t)w * 32 + lane]);
    int i = beg;
    for (; i + 8 <= end; i += 8) {
        int r0 = g_rows[i],     r1 = g_rows[i + 1], r2 = g_rows[i + 2], r3 = g_rows[i + 3];
        int r4 = g_rows[i + 4], r5 = g_rows[i + 5], r6 = g_rows[i + 6], r7 = g_rows[i + 7];
        float v0 = __half2float(g_s2h[(size_t)r0 * 32 + lane]);
        float v1 = __half2float(g_s2h[(size_t)r1 * 32 + lane]);
        float v2 = __half2float(g_s2h[(size_t)r2 * 32 + lane]);
        float v3 = __half2float(g_s2h[(size_t)r3 * 32 + lane]);
        float v4 = __half2float(g_s2h[(size_t)r4 * 32 + lane]);
        float v5 = __half2float(g_s2h[(size_t)r5 * 32 + lane]);
        float v6 = __half2float(g_s2h[(size_t)r6 * 32 + lane]);
        float v7 = __half2float(g_s2h[(size_t)r7 * 32 + lane]);
        acc += ((v0 + v1) + (v2 + v3)) + ((v4 + v5) + (v6 + v7));
    }
    for (; i < end; i++) acc += __half2float(g_s2h[(size_t)g_rows[i] * 32 + lane]);
    g_z2[(size_t)w * 32 + lane] = fmaf(g_dinv[w], acc, b2[lane]);
}

// ---------------- decode: out[p] = dot(z2[a], z2[b]) over 32 dims ----------------
__global__ __launch_bounds__(256) void k_decode(const void* __restrict__ eli,
                                                float* __restrict__ out, int EL) {
    int t = blockIdx.x * blockDim.x + threadIdx.x;
    int p = t >> 3;
    int j = t & 7;
    if (p >= EL) return;
    int is32 = g_is32;
    int a = edge_at(eli, p, is32);
    int b = edge_at(eli, (long long)EL + p, is32);
    float4 va = ((const float4*)g_z2)[a * 8 + j];
    float4 vb = ((const float4*)g_z2)[b * 8 + j];
    float s = va.x * vb.x + va.y * vb.y + va.z * vb.z + va.w * vb.w;
    s += __shfl_down_sync(0xffffffffu, s, 4, 8);
    s += __shfl_down_sync(0xffffffffu, s, 2, 8);
    s += __shfl_down_sync(0xffffffffu, s, 1, 8);
    if (j == 0) out[p] = s;
}

// ---------------- launch ----------------
extern "C" void kernel_launch(void* const* d_in, const int* in_sizes, int n_in,
                              void* d_out, int out_size) {
    const float* x   = (const float*)d_in[0];
    const float* W1  = (const float*)d_in[1];
    const float* b1  = (const float*)d_in[2];
    const float* W2  = (const float*)d_in[3];
    const float* b2  = (const float*)d_in[4];
    const void*  ei  = d_in[5];
    const void*  eli = d_in[6];

    int H  = in_sizes[2];                 // 64
    int F  = in_sizes[1] / H;             // 128
    int N  = in_sizes[0] / F;             // 100000
    int E  = in_sizes[5] / 2;             // 3200000
    int EL = in_sizes[6] / 2;             // 200000
    float* out = (float*)d_out;

    int NB1024 = (N + 1023) / 1024;
    int gemm1_smem = (FDIM * HDIM + FDIM * XSTR) * sizeof(float);   // ~66KB
    cudaFuncSetAttribute(k_gemm1, cudaFuncAttributeMaxDynamicSharedMemorySize, gemm1_smem);

    // CSR build (reused for both layers)
    k_prep<<<(N + 255) / 256, 256>>>(ei, E, N);
    k_count<<<(E + 511) / 512, 512>>>(ei, E);
    k_scanA<<<NB1024, 1024>>>(N);
    k_scanB<<<1, 1024>>>(NB1024);
    k_scanC<<<NB1024, 1024>>>(N, E);
    k_fill<<<(E + 511) / 512, 512>>>(ei, E);

    // layer 1 (gemm) + fused (agg1 + gemm2)
    k_gemm1<<<(N + 63) / 64, 256, gemm1_smem>>>(x, W1, N);
    k_agg1g2<<<(N + 7) / 8, 256>>>(b1, W2, N);

    // layer 2 aggregation
    k_agg2<<<(N + 7) / 8, 256>>>(b2, N);

    // link decode
    k_decode<<<(EL * 8 + 255) / 256, 256>>>(eli, out, EL);
}

// round 5
// speedup vs baseline: 1.0139x; 1.0139x over previous
#include <cuda_runtime.h>
#include <cuda_fp16.h>

// ---------------- fixed problem capacities (dataset is fixed) ----------------
#define NMAX 100000
#define EMAX 3200000
#define HDIM 64
#define ODIM 32
#define FDIM 128
#define XSTR 65   // padded [k][n] stride: conflict-free stage-write and read

// ---------------- device scratch (no allocations allowed) ----------------
__device__ int   g_is32;                              // 1 if edge indices are int32
__device__ int   g_ecnt[NMAX];                        // in-degree (no self loop)
__device__ int   g_ptr[NMAX + 1];                     // CSR offsets
__device__ int   g_cursor[NMAX];                      // fill cursors
__device__ unsigned long long g_scanstate[128];       // lookback: (flag<<32)|sum
__device__ float g_dinv[NMAX];                        // 1/sqrt(deg+1)
__device__ __align__(16) int     g_rows[EMAX];        // CSR adjacency: src per slot
__device__ __align__(16) __half2 g_s1h[NMAX * 32];    // fp16 dinv*(x@W1): 64 vals/node
__device__ __align__(16) float   g_z1[NMAX * HDIM];   // relu layer-1 output (fp32)
__device__ __align__(16) __half  g_s2h[NMAX * ODIM];  // fp16 dinv*(z1@W2): 32 vals/node
__device__ __align__(16) float   g_z2[NMAX * ODIM];   // layer-2 output (fp32)

// fetch edge value j from a buffer that is either int32[2E] or int64[2E]
__device__ __forceinline__ int edge_at(const void* p, long long j, int is32) {
    if (is32) return ((const int*)p)[j];
    return (int)((const long long*)p)[j];
}

// ---------------- prep: dtype detect + zero counters/flags ----------------
__global__ void k_prep(const void* ei, int E, int N) {
    int i = blockIdx.x * blockDim.x + threadIdx.x;
    if (i < N) g_ecnt[i] = 0;
    if (i < 128) g_scanstate[i] = 0ull;
    if (blockIdx.x == 0) {
        __shared__ int bad;
        if (threadIdx.x == 0) bad = 0;
        __syncthreads();
        int n = (2 * E < 256) ? 2 * E : 256;
        if (threadIdx.x < n) {
            long long v = ((const long long*)ei)[threadIdx.x];
            if (v < 0 || v >= NMAX) atomicOr(&bad, 1);
        }
        __syncthreads();
        if (threadIdx.x == 0) g_is32 = bad;
    }
}

__global__ void k_count(const void* __restrict__ ei, int E) {
    int e = blockIdx.x * blockDim.x + threadIdx.x;
    if (e < E) {
        int c = edge_at(ei, (long long)E + e, g_is32);
        atomicAdd(&g_ecnt[c], 1);
    }
}

// ---- single-pass exclusive scan (decoupled lookback), + cursor + dinv ----
__global__ void k_scan(int N, int E) {
    __shared__ int sh[1024];
    __shared__ int s_prefix;
    int t = threadIdx.x, b = blockIdx.x;
    int i = b * 1024 + t;
    int v = (i < N) ? g_ecnt[i] : 0;
    sh[t] = v;
    __syncthreads();
    for (int off = 1; off < 1024; off <<= 1) {
        int y = 0;
        if (t >= off) y = sh[t - off];
        __syncthreads();
        sh[t] += y;
        __syncthreads();
    }
    if (t == 0) {
        unsigned long long total = (unsigned long long)(unsigned int)sh[1023];
        if (b == 0) {
            // inclusive published directly (flag=2)
            atomicExch(&g_scanstate[0], (2ull << 32) | total);
            s_prefix = 0;
        } else {
            // publish aggregate (flag=1)
            atomicExch(&g_scanstate[b], (1ull << 32) | total);
            long long pref = 0;
            for (int j = b - 1; j >= 0;) {
                unsigned long long s;
                do { s = atomicAdd(&g_scanstate[j], 0ull); } while ((s >> 32) == 0);
                if ((s >> 32) == 2ull) { pref += (long long)(s & 0xffffffffull); break; }
                pref += (long long)(s & 0xffffffffull);
                j--;
            }
            atomicExch(&g_scanstate[b],
                       (2ull << 32) | (unsigned long long)(unsigned int)(pref + (long long)total));
            s_prefix = (int)pref;
        }
    }
    __syncthreads();
    int p = s_prefix + sh[t] - v;          // global exclusive prefix
    if (i < N) {
        g_ptr[i] = p;
        g_cursor[i] = p;
        g_dinv[i] = rsqrtf((float)(g_ecnt[i] + 1));   // +1 self loop
    }
    if (i == 0) g_ptr[N] = E;
}

__global__ void k_fill(const void* __restrict__ ei, int E) {
    int e = blockIdx.x * blockDim.x + threadIdx.x;
    if (e < E) {
        int is32 = g_is32;
        int r = edge_at(ei, e, is32);
        int c = edge_at(ei, (long long)E + e, is32);
        int pos = atomicAdd(&g_cursor[c], 1);
        g_rows[pos] = r;
    }
}

// ---------------- GEMM1: s1h = fp16( dinv * (x @ W1) )   [N,128]x[128,64] ----------------
__global__ __launch_bounds__(256) void k_gemm1(const float* __restrict__ x,
                                               const float* __restrict__ W1, int N) {
    extern __shared__ float sm[];
    float* Ws = sm;                         // [128][64] row-major, 32KB
    float* xs = sm + FDIM * HDIM;           // [k][n] stride XSTR
    int t = threadIdx.x;
    for (int i = t; i < FDIM * HDIM; i += 256) Ws[i] = W1[i];

    int node0 = blockIdx.x * 64;
    int lane = t & 31, wrp = t >> 5;
#pragma unroll
    for (int rep = 0; rep < 32; rep++) {
        int n = wrp * 8 + (rep >> 2);
        int k = (rep & 3) * 32 + lane;
        int gn = node0 + n;
        float v = (gn < N) ? x[(size_t)gn * FDIM + k] : 0.f;
        xs[k * XSTR + n] = v;
    }
    __syncthreads();

    int n = t & 63;
    int og = t >> 6;
    float acc[16];
#pragma unroll
    for (int i = 0; i < 16; i++) acc[i] = 0.f;
    const float4* Ws4 = (const float4*)Ws;
#pragma unroll 4
    for (int k = 0; k < FDIM; k++) {
        float xv = xs[k * XSTR + n];
        float4 w0 = Ws4[k * 16 + og * 4 + 0];
        float4 w1 = Ws4[k * 16 + og * 4 + 1];
        float4 w2 = Ws4[k * 16 + og * 4 + 2];
        float4 w3 = Ws4[k * 16 + og * 4 + 3];
        acc[0]  = fmaf(xv, w0.x, acc[0]);  acc[1]  = fmaf(xv, w0.y, acc[1]);
        acc[2]  = fmaf(xv, w0.z, acc[2]);  acc[3]  = fmaf(xv, w0.w, acc[3]);
        acc[4]  = fmaf(xv, w1.x, acc[4]);  acc[5]  = fmaf(xv, w1.y, acc[5]);
        acc[6]  = fmaf(xv, w1.z, acc[6]);  acc[7]  = fmaf(xv, w1.w, acc[7]);
        acc[8]  = fmaf(xv, w2.x, acc[8]);  acc[9]  = fmaf(xv, w2.y, acc[9]);
        acc[10] = fmaf(xv, w2.z, acc[10]); acc[11] = fmaf(xv, w2.w, acc[11]);
        acc[12] = fmaf(xv, w3.x, acc[12]); acc[13] = fmaf(xv, w3.y, acc[13]);
        acc[14] = fmaf(xv, w3.z, acc[14]); acc[15] = fmaf(xv, w3.w, acc[15]);
    }
    int gn = node0 + n;
    if (gn < N) {
        float d = g_dinv[gn];
        unsigned int p[8];
#pragma unroll
        for (int j = 0; j < 8; j++) {
            __half2 h = __floats2half2_rn(d * acc[2 * j], d * acc[2 * j + 1]);
            p[j] = *(unsigned int*)&h;
        }
        uint4* dst = (uint4*)(g_s1h + (size_t)gn * 32 + og * 8);
        dst[0] = make_uint4(p[0], p[1], p[2], p[3]);
        dst[1] = make_uint4(p[4], p[5], p[6], p[7]);
    }
}

// ---------------- agg1: z1 = relu(dinv*(sum_nbrs s1h + self) + b1) ----------------
__global__ __launch_bounds__(256) void k_agg1(const float* __restrict__ b1, int N) {
    int w = (blockIdx.x * blockDim.x + threadIdx.x) >> 5;
    int lane = threadIdx.x & 31;
    if (w >= N) return;
    int beg = g_ptr[w], end = g_ptr[w + 1];
    float2 a = __half22float2(g_s1h[(size_t)w * 32 + lane]);   // self
    float ax = a.x, ay = a.y;
    int i = beg;
    for (; i + 8 <= end; i += 8) {
        int r0 = g_rows[i],     r1 = g_rows[i + 1], r2 = g_rows[i + 2], r3 = g_rows[i + 3];
        int r4 = g_rows[i + 4], r5 = g_rows[i + 5], r6 = g_rows[i + 6], r7 = g_rows[i + 7];
        float2 v0 = __half22float2(g_s1h[(size_t)r0 * 32 + lane]);
        float2 v1 = __half22float2(g_s1h[(size_t)r1 * 32 + lane]);
        float2 v2 = __half22float2(g_s1h[(size_t)r2 * 32 + lane]);
        float2 v3 = __half22float2(g_s1h[(size_t)r3 * 32 + lane]);
        float2 v4 = __half22float2(g_s1h[(size_t)r4 * 32 + lane]);
        float2 v5 = __half22float2(g_s1h[(size_t)r5 * 32 + lane]);
        float2 v6 = __half22float2(g_s1h[(size_t)r6 * 32 + lane]);
        float2 v7 = __half22float2(g_s1h[(size_t)r7 * 32 + lane]);
        ax += ((v0.x + v1.x) + (v2.x + v3.x)) + ((v4.x + v5.x) + (v6.x + v7.x));
        ay += ((v0.y + v1.y) + (v2.y + v3.y)) + ((v4.y + v5.y) + (v6.y + v7.y));
    }
    for (; i < end; i++) {
        float2 v = __half22float2(g_s1h[(size_t)g_rows[i] * 32 + lane]);
        ax += v.x; ay += v.y;
    }
    float d = g_dinv[w];
    float2 bb = ((const float2*)b1)[lane];
    float zx = fmaxf(fmaf(d, ax, bb.x), 0.f);
    float zy = fmaxf(fmaf(d, ay, bb.y), 0.f);
    ((float2*)g_z1)[(size_t)w * 32 + lane] = make_float2(zx, zy);
}

// ---------------- GEMM2: s2h = fp16( dinv * (z1 @ W2) )   [N,64]x[64,32] ----------------
__global__ __launch_bounds__(256) void k_gemm2(const float* __restrict__ W2, int N) {
    __shared__ float Ws[HDIM * ODIM];         // 8KB
    __shared__ float zs[HDIM * XSTR];         // [k][n]
    int t = threadIdx.x;
    for (int i = t; i < HDIM * ODIM; i += 256) Ws[i] = W2[i];

    int node0 = blockIdx.x * 64;
    int lane = t & 31, wrp = t >> 5;
#pragma unroll
    for (int rep = 0; rep < 16; rep++) {
        int n = wrp * 8 + (rep >> 1);
        int k = (rep & 1) * 32 + lane;
        int gn = node0 + n;
        float v = (gn < N) ? g_z1[(size_t)gn * HDIM + k] : 0.f;
        zs[k * XSTR + n] = v;
    }
    __syncthreads();

    int n = t & 63;
    int og = t >> 6;                          // 0..3, outputs og*8 .. og*8+7
    float acc[8];
#pragma unroll
    for (int i = 0; i < 8; i++) acc[i] = 0.f;
    const float4* Ws4 = (const float4*)Ws;
#pragma unroll 4
    for (int k = 0; k < HDIM; k++) {
        float xv = zs[k * XSTR + n];
        float4 w0 = Ws4[k * 8 + og * 2];
        float4 w1 = Ws4[k * 8 + og * 2 + 1];
        acc[0] = fmaf(xv, w0.x, acc[0]); acc[1] = fmaf(xv, w0.y, acc[1]);
        acc[2] = fmaf(xv, w0.z, acc[2]); acc[3] = fmaf(xv, w0.w, acc[3]);
        acc[4] = fmaf(xv, w1.x, acc[4]); acc[5] = fmaf(xv, w1.y, acc[5]);
        acc[6] = fmaf(xv, w1.z, acc[6]); acc[7] = fmaf(xv, w1.w, acc[7]);
    }
    int gn = node0 + n;
    if (gn < N) {
        float d = g_dinv[gn];
        unsigned int p[4];
#pragma unroll
        for (int j = 0; j < 4; j++) {
            __half2 h = __floats2half2_rn(d * acc[2 * j], d * acc[2 * j + 1]);
            p[j] = *(unsigned int*)&h;
        }
        *(uint4*)(g_s2h + (size_t)gn * ODIM + og * 8) = make_uint4(p[0], p[1], p[2], p[3]);
    }
}

// ---------------- agg2: z2 = dinv*(sum + self) + b2  (fp16 gather) ----------------
__global__ __launch_bounds__(256) void k_agg2(const float* __restrict__ b2, int N) {
    int w = (blockIdx.x * blockDim.x + threadIdx.x) >> 5;
    int lane = threadIdx.x & 31;
    if (w >= N) return;
    int beg = g_ptr[w], end = g_ptr[w + 1];
    float acc = __half2float(g_s2h[(size_t)w * 32 + lane]);
    int i = beg;
    for (; i + 8 <= end; i += 8) {
        int r0 = g_rows[i],     r1 = g_rows[i + 1], r2 = g_rows[i + 2], r3 = g_rows[i + 3];
        int r4 = g_rows[i + 4], r5 = g_rows[i + 5], r6 = g_rows[i + 6], r7 = g_rows[i + 7];
        float v0 = __half2float(g_s2h[(size_t)r0 * 32 + lane]);
        float v1 = __half2float(g_s2h[(size_t)r1 * 32 + lane]);
        float v2 = __half2float(g_s2h[(size_t)r2 * 32 + lane]);
        float v3 = __half2float(g_s2h[(size_t)r3 * 32 + lane]);
        float v4 = __half2float(g_s2h[(size_t)r4 * 32 + lane]);
        float v5 = __half2float(g_s2h[(size_t)r5 * 32 + lane]);
        float v6 = __half2float(g_s2h[(size_t)r6 * 32 + lane]);
        float v7 = __half2float(g_s2h[(size_t)r7 * 32 + lane]);
        acc += ((v0 + v1) + (v2 + v3)) + ((v4 + v5) + (v6 + v7));
    }
    for (; i < end; i++) acc += __half2float(g_s2h[(size_t)g_rows[i] * 32 + lane]);
    g_z2[(size_t)w * 32 + lane] = fmaf(g_dinv[w], acc, b2[lane]);
}

// ---------------- decode: out[p] = dot(z2[a], z2[b]) over 32 dims ----------------
__global__ __launch_bounds__(256) void k_decode(const void* __restrict__ eli,
                                                float* __restrict__ out, int EL) {
    int t = blockIdx.x * blockDim.x + threadIdx.x;
    int p = t >> 3;
    int j = t & 7;
    if (p >= EL) return;
    int is32 = g_is32;
    int a = edge_at(eli, p, is32);
    int b = edge_at(eli, (long long)EL + p, is32);
    float4 va = ((const float4*)g_z2)[a * 8 + j];
    float4 vb = ((const float4*)g_z2)[b * 8 + j];
    float s = va.x * vb.x + va.y * vb.y + va.z * vb.z + va.w * vb.w;
    s += __shfl_down_sync(0xffffffffu, s, 4, 8);
    s += __shfl_down_sync(0xffffffffu, s, 2, 8);
    s += __shfl_down_sync(0xffffffffu, s, 1, 8);
    if (j == 0) out[p] = s;
}

// ---------------- launch ----------------
extern "C" void kernel_launch(void* const* d_in, const int* in_sizes, int n_in,
                              void* d_out, int out_size) {
    const float* x   = (const float*)d_in[0];
    const float* W1  = (const float*)d_in[1];
    const float* b1  = (const float*)d_in[2];
    const float* W2  = (const float*)d_in[3];
    const float* b2  = (const float*)d_in[4];
    const void*  ei  = d_in[5];
    const void*  eli = d_in[6];

    int H  = in_sizes[2];                 // 64
    int F  = in_sizes[1] / H;             // 128
    int N  = in_sizes[0] / F;             // 100000
    int E  = in_sizes[5] / 2;             // 3200000
    int EL = in_sizes[6] / 2;             // 200000
    float* out = (float*)d_out;

    int NB1024 = (N + 1023) / 1024;
    int gemm1_smem = (FDIM * HDIM + FDIM * XSTR) * sizeof(float);   // ~66KB
    cudaFuncSetAttribute(k_gemm1, cudaFuncAttributeMaxDynamicSharedMemorySize, gemm1_smem);

    // side stream + events for fork/join (capture-time host objects; replay cost 0)
    cudaStream_t s2;
    cudaStreamCreateWithFlags(&s2, cudaStreamNonBlocking);
    cudaEvent_t ev_fork, ev_join;
    cudaEventCreateWithFlags(&ev_fork, cudaEventDisableTiming);
    cudaEventCreateWithFlags(&ev_join, cudaEventDisableTiming);

    // CSR build prefix (main stream)
    k_prep<<<(N + 255) / 256, 256>>>(ei, E, N);
    k_count<<<(E + 511) / 512, 512>>>(ei, E);
    k_scan<<<NB1024, 1024>>>(N, E);

    // fork: gemm1 (needs dinv only) runs concurrently with fill
    cudaEventRecord(ev_fork, 0);
    cudaStreamWaitEvent(s2, ev_fork, 0);
    k_gemm1<<<(N + 63) / 64, 256, gemm1_smem, s2>>>(x, W1, N);
    k_fill<<<(E + 511) / 512, 512>>>(ei, E);
    cudaEventRecord(ev_join, s2);
    cudaStreamWaitEvent(0, ev_join, 0);

    // layer 1 aggregation, layer 2 gemm + aggregation
    k_agg1<<<(N + 7) / 8, 256>>>(b1, N);
    k_gemm2<<<(N + 63) / 64, 256>>>(W2, N);
    k_agg2<<<(N + 7) / 8, 256>>>(b2, N);

    // link decode
    k_decode<<<(EL * 8 + 255) / 256, 256>>>(eli, out, EL);

    cudaEventDestroy(ev_fork);
    cudaEventDestroy(ev_join);
    cudaStreamDestroy(s2);
}

// round 6
// speedup vs baseline: 1.2452x; 1.2282x over previous
#include <cuda_runtime.h>
#include <cuda_fp16.h>

// ---------------- fixed problem capacities (dataset is fixed) ----------------
#define NMAX 100000
#define EMAX 3200000
#define HDIM 64
#define ODIM 32
#define FDIM 128
#define XSTR 65    // padded fp32 [k][n] stride (gemm2)
#define HPAD 68    // padded half2/uint stride (=136 halves) for tensor gemm smem

// ---------------- device scratch (no allocations allowed) ----------------
__device__ int   g_is32;                              // 1 if edge indices are int32
__device__ int   g_ecnt[NMAX];                        // in-degree (no self loop)
__device__ int   g_ptr[NMAX + 1];                     // CSR offsets
__device__ int   g_cursor[NMAX];                      // fill cursors
__device__ unsigned long long g_scanstate[128];       // lookback: (flag<<32)|sum
__device__ float g_dinv[NMAX];                        // 1/sqrt(deg+1)
__device__ __align__(16) int     g_rows[EMAX];        // CSR adjacency: src per slot
__device__ __align__(16) __half2 g_s1h[NMAX * 32];    // fp16 dinv*(x@W1): 64 vals/node
__device__ __align__(16) float   g_z1[NMAX * HDIM];   // relu layer-1 output (fp32)
__device__ __align__(16) __half  g_s2h[NMAX * ODIM];  // fp16 dinv*(z1@W2): 32 vals/node
__device__ __align__(16) float   g_z2[NMAX * ODIM];   // layer-2 output (fp32)

__device__ __forceinline__ int edge_at(const void* p, long long j, int is32) {
    if (is32) return ((const int*)p)[j];
    return (int)((const long long*)p)[j];
}
__device__ __forceinline__ unsigned int pack_h2(float a, float b) {
    __half2 h = __floats2half2_rn(a, b);
    return *reinterpret_cast<unsigned int*>(&h);
}

// ---------------- prep: dtype detect + zero counters/flags ----------------
__global__ void k_prep(const void* ei, int E, int N) {
    int i = blockIdx.x * blockDim.x + threadIdx.x;
    if (i < N) g_ecnt[i] = 0;
    if (i < 128) g_scanstate[i] = 0ull;
    if (blockIdx.x == 0) {
        __shared__ int bad;
        if (threadIdx.x == 0) bad = 0;
        __syncthreads();
        int n = (2 * E < 256) ? 2 * E : 256;
        if (threadIdx.x < n) {
            long long v = ((const long long*)ei)[threadIdx.x];
            if (v < 0 || v >= NMAX) atomicOr(&bad, 1);
        }
        __syncthreads();
        if (threadIdx.x == 0) g_is32 = bad;
    }
}

__global__ void k_count(const void* __restrict__ ei, int E) {
    int e = blockIdx.x * blockDim.x + threadIdx.x;
    if (e < E) {
        int c = edge_at(ei, (long long)E + e, g_is32);
        atomicAdd(&g_ecnt[c], 1);
    }
}

// ---- single-pass exclusive scan (decoupled lookback), + cursor + dinv ----
__global__ void k_scan(int N, int E) {
    __shared__ int sh[1024];
    __shared__ int s_prefix;
    int t = threadIdx.x, b = blockIdx.x;
    int i = b * 1024 + t;
    int v = (i < N) ? g_ecnt[i] : 0;
    sh[t] = v;
    __syncthreads();
    for (int off = 1; off < 1024; off <<= 1) {
        int y = 0;
        if (t >= off) y = sh[t - off];
        __syncthreads();
        sh[t] += y;
        __syncthreads();
    }
    if (t == 0) {
        unsigned long long total = (unsigned long long)(unsigned int)sh[1023];
        if (b == 0) {
            atomicExch(&g_scanstate[0], (2ull << 32) | total);
            s_prefix = 0;
        } else {
            atomicExch(&g_scanstate[b], (1ull << 32) | total);
            long long pref = 0;
            for (int j = b - 1; j >= 0;) {
                unsigned long long s;
                do { s = atomicAdd(&g_scanstate[j], 0ull); } while ((s >> 32) == 0);
                if ((s >> 32) == 2ull) { pref += (long long)(s & 0xffffffffull); break; }
                pref += (long long)(s & 0xffffffffull);
                j--;
            }
            atomicExch(&g_scanstate[b],
                       (2ull << 32) | (unsigned long long)(unsigned int)(pref + (long long)total));
            s_prefix = (int)pref;
        }
    }
    __syncthreads();
    int p = s_prefix + sh[t] - v;
    if (i < N) {
        g_ptr[i] = p;
        g_cursor[i] = p;
        g_dinv[i] = rsqrtf((float)(g_ecnt[i] + 1));
    }
    if (i == 0) g_ptr[N] = E;
}

__global__ void k_fill(const void* __restrict__ ei, int E) {
    int e = blockIdx.x * blockDim.x + threadIdx.x;
    if (e < E) {
        int is32 = g_is32;
        int r = edge_at(ei, e, is32);
        int c = edge_at(ei, (long long)E + e, is32);
        int pos = atomicAdd(&g_cursor[c], 1);
        g_rows[pos] = r;
    }
}

// ---------------- GEMM1 (tensor cores): s1h = fp16( dinv * (x @ W1) ) ----------------
// 128 nodes/block, 256 threads = 8 warps; warp w computes nodes [w*16, w*16+16).
// mma.m16n8k16 fp16->fp32. smem rows padded to 136 halves (68 uints): fragment
// loads hit 32 distinct banks (68 mod 32 = 4; 4*g + t covers 0..31).
__global__ __launch_bounds__(256) void k_gemm1(const float* __restrict__ x,
                                               const float* __restrict__ W1, int N) {
    extern __shared__ unsigned int smu[];
    unsigned int* xh = smu;                 // [128][HPAD] uints (half2)
    unsigned int* wh = smu + 128 * HPAD;    // [64][HPAD]  uints: W1 transposed [n][k]
    __half* whh = (__half*)wh;
    int t = threadIdx.x;

    // stage W1^T as fp16: whh[n*136 + k] = W1[k][n]
    for (int i = t; i < FDIM * HDIM; i += 256) {
        int k = i >> 6, n = i & 63;
        whh[n * (2 * HPAD) + k] = __float2half_rn(W1[i]);
    }
    // stage x as fp16: xh[node][k]
    int node0 = blockIdx.x * 128;
    const float4* x4 = (const float4*)x;
    for (int i = t; i < 128 * 32; i += 256) {
        int nd = i >> 5, kq = i & 31;
        int gn = node0 + nd;
        float4 v = (gn < N) ? x4[(size_t)gn * 32 + kq] : make_float4(0.f, 0.f, 0.f, 0.f);
        xh[nd * HPAD + kq * 2]     = pack_h2(v.x, v.y);
        xh[nd * HPAD + kq * 2 + 1] = pack_h2(v.z, v.w);
    }
    __syncthreads();

    int wid = t >> 5, lane = t & 31;
    int g = lane >> 2, tq = lane & 3;
    int nodeW = wid * 16;

    // A fragments for all 8 k-steps (16x16 each)
    unsigned int A[8][4];
#pragma unroll
    for (int ks = 0; ks < 8; ks++) {
        int base0 = (nodeW + g) * HPAD + ks * 8 + tq;
        int base1 = (nodeW + g + 8) * HPAD + ks * 8 + tq;
        A[ks][0] = xh[base0];
        A[ks][1] = xh[base1];
        A[ks][2] = xh[base0 + 4];
        A[ks][3] = xh[base1 + 4];
    }

    float acc[8][4];
#pragma unroll
    for (int nt = 0; nt < 8; nt++)
#pragma unroll
        for (int j = 0; j < 4; j++) acc[nt][j] = 0.f;

#pragma unroll
    for (int nt = 0; nt < 8; nt++) {
        int brow = (nt * 8 + g) * HPAD + tq;
#pragma unroll
        for (int ks = 0; ks < 8; ks++) {
            unsigned int b0 = wh[brow + ks * 8];
            unsigned int b1 = wh[brow + ks * 8 + 4];
            asm volatile(
                "mma.sync.aligned.m16n8k16.row.col.f32.f16.f16.f32 "
                "{%0,%1,%2,%3}, {%4,%5,%6,%7}, {%8,%9}, {%0,%1,%2,%3};"
                : "+f"(acc[nt][0]), "+f"(acc[nt][1]), "+f"(acc[nt][2]), "+f"(acc[nt][3])
                : "r"(A[ks][0]), "r"(A[ks][1]), "r"(A[ks][2]), "r"(A[ks][3]),
                  "r"(b0), "r"(b1));
        }
    }

    // epilogue: scale by dinv, fp16, store. c0,c1 -> row g; c2,c3 -> row g+8.
    int gn0 = node0 + nodeW + g;
    int gn1 = gn0 + 8;
    float d0 = (gn0 < N) ? g_dinv[gn0] : 0.f;
    float d1 = (gn1 < N) ? g_dinv[gn1] : 0.f;
    unsigned int* s1u = (unsigned int*)g_s1h;
#pragma unroll
    for (int nt = 0; nt < 8; nt++) {
        int ch = (nt * 8 + tq * 2) >> 1;   // half2 column index
        if (gn0 < N) s1u[(size_t)gn0 * 32 + ch] = pack_h2(d0 * acc[nt][0], d0 * acc[nt][1]);
        if (gn1 < N) s1u[(size_t)gn1 * 32 + ch] = pack_h2(d1 * acc[nt][2], d1 * acc[nt][3]);
    }
}

// ---------------- agg1: z1 = relu(dinv*(sum_nbrs s1h + self) + b1) ----------------
__global__ __launch_bounds__(256) void k_agg1(const float* __restrict__ b1, int N) {
    int w = (blockIdx.x * blockDim.x + threadIdx.x) >> 5;
    int lane = threadIdx.x & 31;
    if (w >= N) return;
    int beg = g_ptr[w], end = g_ptr[w + 1];
    float2 a = __half22float2(g_s1h[(size_t)w * 32 + lane]);
    float ax = a.x, ay = a.y;
    int i = beg;
    for (; i + 8 <= end; i += 8) {
        int r0 = g_rows[i],     r1 = g_rows[i + 1], r2 = g_rows[i + 2], r3 = g_rows[i + 3];
        int r4 = g_rows[i + 4], r5 = g_rows[i + 5], r6 = g_rows[i + 6], r7 = g_rows[i + 7];
        float2 v0 = __half22float2(g_s1h[(size_t)r0 * 32 + lane]);
        float2 v1 = __half22float2(g_s1h[(size_t)r1 * 32 + lane]);
        float2 v2 = __half22float2(g_s1h[(size_t)r2 * 32 + lane]);
        float2 v3 = __half22float2(g_s1h[(size_t)r3 * 32 + lane]);
        float2 v4 = __half22float2(g_s1h[(size_t)r4 * 32 + lane]);
        float2 v5 = __half22float2(g_s1h[(size_t)r5 * 32 + lane]);
        float2 v6 = __half22float2(g_s1h[(size_t)r6 * 32 + lane]);
        float2 v7 = __half22float2(g_s1h[(size_t)r7 * 32 + lane]);
        ax += ((v0.x + v1.x) + (v2.x + v3.x)) + ((v4.x + v5.x) + (v6.x + v7.x));
        ay += ((v0.y + v1.y) + (v2.y + v3.y)) + ((v4.y + v5.y) + (v6.y + v7.y));
    }
    for (; i < end; i++) {
        float2 v = __half22float2(g_s1h[(size_t)g_rows[i] * 32 + lane]);
        ax += v.x; ay += v.y;
    }
    float d = g_dinv[w];
    float2 bb = ((const float2*)b1)[lane];
    float zx = fmaxf(fmaf(d, ax, bb.x), 0.f);
    float zy = fmaxf(fmaf(d, ay, bb.y), 0.f);
    ((float2*)g_z1)[(size_t)w * 32 + lane] = make_float2(zx, zy);
}

// ---------------- GEMM2: s2h = fp16( dinv * (z1 @ W2) )   [N,64]x[64,32] ----------------
__global__ __launch_bounds__(256) void k_gemm2(const float* __restrict__ W2, int N) {
    __shared__ float Ws[HDIM * ODIM];
    __shared__ float zs[HDIM * XSTR];
    int t = threadIdx.x;
    for (int i = t; i < HDIM * ODIM; i += 256) Ws[i] = W2[i];

    int node0 = blockIdx.x * 64;
    int lane = t & 31, wrp = t >> 5;
#pragma unroll
    for (int rep = 0; rep < 16; rep++) {
        int n = wrp * 8 + (rep >> 1);
        int k = (rep & 1) * 32 + lane;
        int gn = node0 + n;
        float v = (gn < N) ? g_z1[(size_t)gn * HDIM + k] : 0.f;
        zs[k * XSTR + n] = v;
    }
    __syncthreads();

    int n = t & 63;
    int og = t >> 6;
    float acc[8];
#pragma unroll
    for (int i = 0; i < 8; i++) acc[i] = 0.f;
    const float4* Ws4 = (const float4*)Ws;
#pragma unroll 4
    for (int k = 0; k < HDIM; k++) {
        float xv = zs[k * XSTR + n];
        float4 w0 = Ws4[k * 8 + og * 2];
        float4 w1 = Ws4[k * 8 + og * 2 + 1];
        acc[0] = fmaf(xv, w0.x, acc[0]); acc[1] = fmaf(xv, w0.y, acc[1]);
        acc[2] = fmaf(xv, w0.z, acc[2]); acc[3] = fmaf(xv, w0.w, acc[3]);
        acc[4] = fmaf(xv, w1.x, acc[4]); acc[5] = fmaf(xv, w1.y, acc[5]);
        acc[6] = fmaf(xv, w1.z, acc[6]); acc[7] = fmaf(xv, w1.w, acc[7]);
    }
    int gn = node0 + n;
    if (gn < N) {
        float d = g_dinv[gn];
        unsigned int p[4];
#pragma unroll
        for (int j = 0; j < 4; j++) p[j] = pack_h2(d * acc[2 * j], d * acc[2 * j + 1]);
        *(uint4*)(g_s2h + (size_t)gn * ODIM + og * 8) = make_uint4(p[0], p[1], p[2], p[3]);
    }
}

// ---------------- agg2: z2 = dinv*(sum + self) + b2  (fp16 gather) ----------------
__global__ __launch_bounds__(256) void k_agg2(const float* __restrict__ b2, int N) {
    int w = (blockIdx.x * blockDim.x + threadIdx.x) >> 5;
    int lane = threadIdx.x & 31;
    if (w >= N) return;
    int beg = g_ptr[w], end = g_ptr[w + 1];
    float acc = __half2float(g_s2h[(size_t)w * 32 + lane]);
    int i = beg;
    for (; i + 8 <= end; i += 8) {
        int r0 = g_rows[i],     r1 = g_rows[i + 1], r2 = g_rows[i + 2], r3 = g_rows[i + 3];
        int r4 = g_rows[i + 4], r5 = g_rows[i + 5], r6 = g_rows[i + 6], r7 = g_rows[i + 7];
        float v0 = __half2float(g_s2h[(size_t)r0 * 32 + lane]);
        float v1 = __half2float(g_s2h[(size_t)r1 * 32 + lane]);
        float v2 = __half2float(g_s2h[(size_t)r2 * 32 + lane]);
        float v3 = __half2float(g_s2h[(size_t)r3 * 32 + lane]);
        float v4 = __half2float(g_s2h[(size_t)r4 * 32 + lane]);
        float v5 = __half2float(g_s2h[(size_t)r5 * 32 + lane]);
        float v6 = __half2float(g_s2h[(size_t)r6 * 32 + lane]);
        float v7 = __half2float(g_s2h[(size_t)r7 * 32 + lane]);
        acc += ((v0 + v1) + (v2 + v3)) + ((v4 + v5) + (v6 + v7));
    }
    for (; i < end; i++) acc += __half2float(g_s2h[(size_t)g_rows[i] * 32 + lane]);
    g_z2[(size_t)w * 32 + lane] = fmaf(g_dinv[w], acc, b2[lane]);
}

// ---------------- decode: out[p] = dot(z2[a], z2[b]) over 32 dims ----------------
__global__ __launch_bounds__(256) void k_decode(const void* __restrict__ eli,
                                                float* __restrict__ out, int EL) {
    int t = blockIdx.x * blockDim.x + threadIdx.x;
    int p = t >> 3;
    int j = t & 7;
    if (p >= EL) return;
    int is32 = g_is32;
    int a = edge_at(eli, p, is32);
    int b = edge_at(eli, (long long)EL + p, is32);
    float4 va = ((const float4*)g_z2)[a * 8 + j];
    float4 vb = ((const float4*)g_z2)[b * 8 + j];
    float s = va.x * vb.x + va.y * vb.y + va.z * vb.z + va.w * vb.w;
    s += __shfl_down_sync(0xffffffffu, s, 4, 8);
    s += __shfl_down_sync(0xffffffffu, s, 2, 8);
    s += __shfl_down_sync(0xffffffffu, s, 1, 8);
    if (j == 0) out[p] = s;
}

// ---------------- launch ----------------
extern "C" void kernel_launch(void* const* d_in, const int* in_sizes, int n_in,
                              void* d_out, int out_size) {
    const float* x   = (const float*)d_in[0];
    const float* W1  = (const float*)d_in[1];
    const float* b1  = (const float*)d_in[2];
    const float* W2  = (const float*)d_in[3];
    const float* b2  = (const float*)d_in[4];
    const void*  ei  = d_in[5];
    const void*  eli = d_in[6];

    int H  = in_sizes[2];                 // 64
    int F  = in_sizes[1] / H;             // 128
    int N  = in_sizes[0] / F;             // 100000
    int E  = in_sizes[5] / 2;             // 3200000
    int EL = in_sizes[6] / 2;             // 200000
    float* out = (float*)d_out;

    int NB1024 = (N + 1023) / 1024;
    int gemm1_smem = (128 * HPAD + 64 * HPAD) * sizeof(unsigned int);   // ~51KB
    cudaFuncSetAttribute(k_gemm1, cudaFuncAttributeMaxDynamicSharedMemorySize, gemm1_smem);

    // side stream + events for fork/join (capture-time host objects; replay cost 0)
    cudaStream_t s2;
    cudaStreamCreateWithFlags(&s2, cudaStreamNonBlocking);
    cudaEvent_t ev_fork, ev_join;
    cudaEventCreateWithFlags(&ev_fork, cudaEventDisableTiming);
    cudaEventCreateWithFlags(&ev_join, cudaEventDisableTiming);

    // CSR build prefix (main stream)
    k_prep<<<(N + 255) / 256, 256>>>(ei, E, N);
    k_count<<<(E + 511) / 512, 512>>>(ei, E);
    k_scan<<<NB1024, 1024>>>(N, E);

    // fork: gemm1 (needs dinv only) runs concurrently with fill
    cudaEventRecord(ev_fork, 0);
    cudaStreamWaitEvent(s2, ev_fork, 0);
    k_gemm1<<<(N + 127) / 128, 256, gemm1_smem, s2>>>(x, W1, N);
    k_fill<<<(E + 511) / 512, 512>>>(ei, E);
    cudaEventRecord(ev_join, s2);
    cudaStreamWaitEvent(0, ev_join, 0);

    // layer 1 aggregation, layer 2 gemm + aggregation
    k_agg1<<<(N + 7) / 8, 256>>>(b1, N);
    k_gemm2<<<(N + 63) / 64, 256>>>(W2, N);
    k_agg2<<<(N + 7) / 8, 256>>>(b2, N);

    // link decode
    k_decode<<<(EL * 8 + 255) / 256, 256>>>(eli, out, EL);

    cudaEventDestroy(ev_fork);
    cudaEventDestroy(ev_join);
    cudaStreamDestroy(s2);
}

// round 7
// speedup vs baseline: 1.2475x; 1.0019x over previous
#include <cuda_runtime.h>
#include <cuda_fp16.h>

// ---------------- fixed problem capacities (dataset is fixed) ----------------
#define NMAX 100000
#define EMAX 3200000
#define HDIM 64
#define ODIM 32
#define FDIM 128
#define XSTR 65    // padded fp32 [k][n] stride (gemm2)
#define HPAD 68    // padded half2/uint stride (=136 halves) for tensor gemm smem

// ---------------- device scratch (no allocations allowed) ----------------
__device__ int   g_is32;                              // 1 if edge indices are int32
__device__ int   g_ecnt[NMAX];                        // in-degree (no self loop)
__device__ int   g_ptr[NMAX + 1];                     // CSR offsets
__device__ int   g_cursor[NMAX];                      // fill cursors
__device__ unsigned long long g_scanstate[128];       // lookback: (flag<<32)|sum
__device__ float g_dinv[NMAX];                        // 1/sqrt(deg+1)
__device__ __align__(16) int     g_rows[EMAX];        // CSR adjacency: src per slot
__device__ __align__(16) __half2 g_s1h[NMAX * 32];    // fp16 dinv*(x@W1): 64 vals/node
__device__ __align__(16) float   g_z1[NMAX * HDIM];   // relu layer-1 output (fp32)
__device__ __align__(16) __half  g_s2h[NMAX * ODIM];  // fp16 dinv*(z1@W2): 32 vals/node
__device__ __align__(16) float   g_z2[NMAX * ODIM];   // layer-2 output (fp32)

__device__ __forceinline__ int edge_at(const void* p, long long j, int is32) {
    if (is32) return ((const int*)p)[j];
    return (int)((const long long*)p)[j];
}
__device__ __forceinline__ unsigned int pack_h2(float a, float b) {
    __half2 h = __floats2half2_rn(a, b);
    return *reinterpret_cast<unsigned int*>(&h);
}

// ---------------- prep: dtype detect + zero counters/flags ----------------
__global__ void k_prep(const void* ei, int E, int N) {
    int i = blockIdx.x * blockDim.x + threadIdx.x;
    if (i < N) g_ecnt[i] = 0;
    if (i < 128) g_scanstate[i] = 0ull;
    if (blockIdx.x == 0) {
        __shared__ int bad;
        if (threadIdx.x == 0) bad = 0;
        __syncthreads();
        int n = (2 * E < 256) ? 2 * E : 256;
        if (threadIdx.x < n) {
            long long v = ((const long long*)ei)[threadIdx.x];
            if (v < 0 || v >= NMAX) atomicOr(&bad, 1);
        }
        __syncthreads();
        if (threadIdx.x == 0) g_is32 = bad;
    }
}

// ---------------- count: 4 edges per thread, vectorized loads ----------------
__global__ void k_count(const void* __restrict__ ei, int E) {
    int q = blockIdx.x * blockDim.x + threadIdx.x;   // quad index
    int e0 = q * 4;
    if (e0 >= E) return;
    int is32 = g_is32;
    if (e0 + 4 <= E) {
        if (is32) {
            int4 c = *(const int4*)((const int*)ei + E + e0);
            atomicAdd(&g_ecnt[c.x], 1);
            atomicAdd(&g_ecnt[c.y], 1);
            atomicAdd(&g_ecnt[c.z], 1);
            atomicAdd(&g_ecnt[c.w], 1);
        } else {
            const longlong2* p = (const longlong2*)((const long long*)ei + E + e0);
            longlong2 a = p[0], b = p[1];
            atomicAdd(&g_ecnt[(int)a.x], 1);
            atomicAdd(&g_ecnt[(int)a.y], 1);
            atomicAdd(&g_ecnt[(int)b.x], 1);
            atomicAdd(&g_ecnt[(int)b.y], 1);
        }
    } else {
        for (int e = e0; e < E; e++)
            atomicAdd(&g_ecnt[edge_at(ei, (long long)E + e, is32)], 1);
    }
}

// ---- single-pass exclusive scan (decoupled lookback), + cursor + dinv ----
__global__ void k_scan(int N, int E) {
    __shared__ int sh[1024];
    __shared__ int s_prefix;
    int t = threadIdx.x, b = blockIdx.x;
    int i = b * 1024 + t;
    int v = (i < N) ? g_ecnt[i] : 0;
    sh[t] = v;
    __syncthreads();
    for (int off = 1; off < 1024; off <<= 1) {
        int y = 0;
        if (t >= off) y = sh[t - off];
        __syncthreads();
        sh[t] += y;
        __syncthreads();
    }
    if (t == 0) {
        unsigned long long total = (unsigned long long)(unsigned int)sh[1023];
        if (b == 0) {
            atomicExch(&g_scanstate[0], (2ull << 32) | total);
            s_prefix = 0;
        } else {
            atomicExch(&g_scanstate[b], (1ull << 32) | total);
            long long pref = 0;
            for (int j = b - 1; j >= 0;) {
                unsigned long long s;
                do { s = atomicAdd(&g_scanstate[j], 0ull); } while ((s >> 32) == 0);
                if ((s >> 32) == 2ull) { pref += (long long)(s & 0xffffffffull); break; }
                pref += (long long)(s & 0xffffffffull);
                j--;
            }
            atomicExch(&g_scanstate[b],
                       (2ull << 32) | (unsigned long long)(unsigned int)(pref + (long long)total));
            s_prefix = (int)pref;
        }
    }
    __syncthreads();
    int p = s_prefix + sh[t] - v;
    if (i < N) {
        g_ptr[i] = p;
        g_cursor[i] = p;
        g_dinv[i] = rsqrtf((float)(g_ecnt[i] + 1));
    }
    if (i == 0) g_ptr[N] = E;
}

// ---------------- fill: 4 edges per thread, vectorized loads ----------------
__global__ void k_fill(const void* __restrict__ ei, int E) {
    int q = blockIdx.x * blockDim.x + threadIdx.x;
    int e0 = q * 4;
    if (e0 >= E) return;
    int is32 = g_is32;
    if (e0 + 4 <= E) {
        int4 r, c;
        if (is32) {
            r = *(const int4*)((const int*)ei + e0);
            c = *(const int4*)((const int*)ei + E + e0);
        } else {
            const longlong2* rp = (const longlong2*)((const long long*)ei + e0);
            const longlong2* cp = (const longlong2*)((const long long*)ei + E + e0);
            longlong2 ra = rp[0], rb = rp[1], ca = cp[0], cb = cp[1];
            r = make_int4((int)ra.x, (int)ra.y, (int)rb.x, (int)rb.y);
            c = make_int4((int)ca.x, (int)ca.y, (int)cb.x, (int)cb.y);
        }
        g_rows[atomicAdd(&g_cursor[c.x], 1)] = r.x;
        g_rows[atomicAdd(&g_cursor[c.y], 1)] = r.y;
        g_rows[atomicAdd(&g_cursor[c.z], 1)] = r.z;
        g_rows[atomicAdd(&g_cursor[c.w], 1)] = r.w;
    } else {
        for (int e = e0; e < E; e++) {
            int rr = edge_at(ei, e, is32);
            int cc = edge_at(ei, (long long)E + e, is32);
            g_rows[atomicAdd(&g_cursor[cc], 1)] = rr;
        }
    }
}

// ---------------- GEMM1 (tensor cores): s1h_raw = fp16( x @ W1 ) ----------------
// No dinv dependency -> can run concurrently with the whole CSR build.
__global__ __launch_bounds__(256) void k_gemm1(const float* __restrict__ x,
                                               const float* __restrict__ W1, int N) {
    extern __shared__ unsigned int smu[];
    unsigned int* xh = smu;                 // [128][HPAD] uints (half2)
    unsigned int* wh = smu + 128 * HPAD;    // [64][HPAD]  uints: W1 transposed [n][k]
    __half* whh = (__half*)wh;
    int t = threadIdx.x;

    for (int i = t; i < FDIM * HDIM; i += 256) {
        int k = i >> 6, n = i & 63;
        whh[n * (2 * HPAD) + k] = __float2half_rn(W1[i]);
    }
    int node0 = blockIdx.x * 128;
    const float4* x4 = (const float4*)x;
    for (int i = t; i < 128 * 32; i += 256) {
        int nd = i >> 5, kq = i & 31;
        int gn = node0 + nd;
        float4 v = (gn < N) ? x4[(size_t)gn * 32 + kq] : make_float4(0.f, 0.f, 0.f, 0.f);
        xh[nd * HPAD + kq * 2]     = pack_h2(v.x, v.y);
        xh[nd * HPAD + kq * 2 + 1] = pack_h2(v.z, v.w);
    }
    __syncthreads();

    int wid = t >> 5, lane = t & 31;
    int g = lane >> 2, tq = lane & 3;
    int nodeW = wid * 16;

    unsigned int A[8][4];
#pragma unroll
    for (int ks = 0; ks < 8; ks++) {
        int base0 = (nodeW + g) * HPAD + ks * 8 + tq;
        int base1 = (nodeW + g + 8) * HPAD + ks * 8 + tq;
        A[ks][0] = xh[base0];
        A[ks][1] = xh[base1];
        A[ks][2] = xh[base0 + 4];
        A[ks][3] = xh[base1 + 4];
    }

    float acc[8][4];
#pragma unroll
    for (int nt = 0; nt < 8; nt++)
#pragma unroll
        for (int j = 0; j < 4; j++) acc[nt][j] = 0.f;

#pragma unroll
    for (int nt = 0; nt < 8; nt++) {
        int brow = (nt * 8 + g) * HPAD + tq;
#pragma unroll
        for (int ks = 0; ks < 8; ks++) {
            unsigned int b0 = wh[brow + ks * 8];
            unsigned int b1 = wh[brow + ks * 8 + 4];
            asm volatile(
                "mma.sync.aligned.m16n8k16.row.col.f32.f16.f16.f32 "
                "{%0,%1,%2,%3}, {%4,%5,%6,%7}, {%8,%9}, {%0,%1,%2,%3};"
                : "+f"(acc[nt][0]), "+f"(acc[nt][1]), "+f"(acc[nt][2]), "+f"(acc[nt][3])
                : "r"(A[ks][0]), "r"(A[ks][1]), "r"(A[ks][2]), "r"(A[ks][3]),
                  "r"(b0), "r"(b1));
        }
    }

    int gn0 = node0 + nodeW + g;
    int gn1 = gn0 + 8;
    unsigned int* s1u = (unsigned int*)g_s1h;
#pragma unroll
    for (int nt = 0; nt < 8; nt++) {
        int ch = (nt * 8 + tq * 2) >> 1;
        if (gn0 < N) s1u[(size_t)gn0 * 32 + ch] = pack_h2(acc[nt][0], acc[nt][1]);
        if (gn1 < N) s1u[(size_t)gn1 * 32 + ch] = pack_h2(acc[nt][2], acc[nt][3]);
    }
}

// ---------------- scale1: s1h *= dinv (fp32 math) ----------------
__global__ void k_scale1(int N) {
    int tid = blockIdx.x * blockDim.x + threadIdx.x;
    int node = tid >> 2, q = tid & 3;
    if (node >= N) return;
    float d = g_dinv[node];
    uint4* p = (uint4*)g_s1h + (size_t)node * 8 + q * 2;
#pragma unroll
    for (int u = 0; u < 2; u++) {
        uint4 v = p[u];
        unsigned int* vi = (unsigned int*)&v;
#pragma unroll
        for (int j = 0; j < 4; j++) {
            float2 f = __half22float2(*(__half2*)&vi[j]);
            vi[j] = pack_h2(d * f.x, d * f.y);
        }
        p[u] = v;
    }
}

// ---------------- agg1: z1 = relu(dinv*(sum_nbrs s1h + self) + b1) ----------------
__global__ __launch_bounds__(256) void k_agg1(const float* __restrict__ b1, int N) {
    int w = (blockIdx.x * blockDim.x + threadIdx.x) >> 5;
    int lane = threadIdx.x & 31;
    if (w >= N) return;
    int beg = g_ptr[w], end = g_ptr[w + 1];
    float2 a = __half22float2(g_s1h[(size_t)w * 32 + lane]);
    float ax = a.x, ay = a.y;
    int i = beg;
    for (; i + 8 <= end; i += 8) {
        int r0 = g_rows[i],     r1 = g_rows[i + 1], r2 = g_rows[i + 2], r3 = g_rows[i + 3];
        int r4 = g_rows[i + 4], r5 = g_rows[i + 5], r6 = g_rows[i + 6], r7 = g_rows[i + 7];
        float2 v0 = __half22float2(g_s1h[(size_t)r0 * 32 + lane]);
        float2 v1 = __half22float2(g_s1h[(size_t)r1 * 32 + lane]);
        float2 v2 = __half22float2(g_s1h[(size_t)r2 * 32 + lane]);
        float2 v3 = __half22float2(g_s1h[(size_t)r3 * 32 + lane]);
        float2 v4 = __half22float2(g_s1h[(size_t)r4 * 32 + lane]);
        float2 v5 = __half22float2(g_s1h[(size_t)r5 * 32 + lane]);
        float2 v6 = __half22float2(g_s1h[(size_t)r6 * 32 + lane]);
        float2 v7 = __half22float2(g_s1h[(size_t)r7 * 32 + lane]);
        ax += ((v0.x + v1.x) + (v2.x + v3.x)) + ((v4.x + v5.x) + (v6.x + v7.x));
        ay += ((v0.y + v1.y) + (v2.y + v3.y)) + ((v4.y + v5.y) + (v6.y + v7.y));
    }
    for (; i < end; i++) {
        float2 v = __half22float2(g_s1h[(size_t)g_rows[i] * 32 + lane]);
        ax += v.x; ay += v.y;
    }
    float d = g_dinv[w];
    float2 bb = ((const float2*)b1)[lane];
    float zx = fmaxf(fmaf(d, ax, bb.x), 0.f);
    float zy = fmaxf(fmaf(d, ay, bb.y), 0.f);
    ((float2*)g_z1)[(size_t)w * 32 + lane] = make_float2(zx, zy);
}

// ---------------- GEMM2: s2h = fp16( dinv * (z1 @ W2) )   [N,64]x[64,32] ----------------
__global__ __launch_bounds__(256) void k_gemm2(const float* __restrict__ W2, int N) {
    __shared__ float Ws[HDIM * ODIM];
    __shared__ float zs[HDIM * XSTR];
    int t = threadIdx.x;
    for (int i = t; i < HDIM * ODIM; i += 256) Ws[i] = W2[i];

    int node0 = blockIdx.x * 64;
    int lane = t & 31, wrp = t >> 5;
#pragma unroll
    for (int rep = 0; rep < 16; rep++) {
        int n = wrp * 8 + (rep >> 1);
        int k = (rep & 1) * 32 + lane;
        int gn = node0 + n;
        float v = (gn < N) ? g_z1[(size_t)gn * HDIM + k] : 0.f;
        zs[k * XSTR + n] = v;
    }
    __syncthreads();

    int n = t & 63;
    int og = t >> 6;
    float acc[8];
#pragma unroll
    for (int i = 0; i < 8; i++) acc[i] = 0.f;
    const float4* Ws4 = (const float4*)Ws;
#pragma unroll 4
    for (int k = 0; k < HDIM; k++) {
        float xv = zs[k * XSTR + n];
        float4 w0 = Ws4[k * 8 + og * 2];
        float4 w1 = Ws4[k * 8 + og * 2 + 1];
        acc[0] = fmaf(xv, w0.x, acc[0]); acc[1] = fmaf(xv, w0.y, acc[1]);
        acc[2] = fmaf(xv, w0.z, acc[2]); acc[3] = fmaf(xv, w0.w, acc[3]);
        acc[4] = fmaf(xv, w1.x, acc[4]); acc[5] = fmaf(xv, w1.y, acc[5]);
        acc[6] = fmaf(xv, w1.z, acc[6]); acc[7] = fmaf(xv, w1.w, acc[7]);
    }
    int gn = node0 + n;
    if (gn < N) {
        float d = g_dinv[gn];
        unsigned int p[4];
#pragma unroll
        for (int j = 0; j < 4; j++) p[j] = pack_h2(d * acc[2 * j], d * acc[2 * j + 1]);
        *(uint4*)(g_s2h + (size_t)gn * ODIM + og * 8) = make_uint4(p[0], p[1], p[2], p[3]);
    }
}

// ---------------- agg2: z2 = dinv*(sum + self) + b2  (fp16 gather) ----------------
__global__ __launch_bounds__(256) void k_agg2(const float* __restrict__ b2, int N) {
    int w = (blockIdx.x * blockDim.x + threadIdx.x) >> 5;
    int lane = threadIdx.x & 31;
    if (w >= N) return;
    int beg = g_ptr[w], end = g_ptr[w + 1];
    float acc = __half2float(g_s2h[(size_t)w * 32 + lane]);
    int i = beg;
    for (; i + 8 <= end; i += 8) {
        int r0 = g_rows[i],     r1 = g_rows[i + 1], r2 = g_rows[i + 2], r3 = g_rows[i + 3];
        int r4 = g_rows[i + 4], r5 = g_rows[i + 5], r6 = g_rows[i + 6], r7 = g_rows[i + 7];
        float v0 = __half2float(g_s2h[(size_t)r0 * 32 + lane]);
        float v1 = __half2float(g_s2h[(size_t)r1 * 32 + lane]);
        float v2 = __half2float(g_s2h[(size_t)r2 * 32 + lane]);
        float v3 = __half2float(g_s2h[(size_t)r3 * 32 + lane]);
        float v4 = __half2float(g_s2h[(size_t)r4 * 32 + lane]);
        float v5 = __half2float(g_s2h[(size_t)r5 * 32 + lane]);
        float v6 = __half2float(g_s2h[(size_t)r6 * 32 + lane]);
        float v7 = __half2float(g_s2h[(size_t)r7 * 32 + lane]);
        acc += ((v0 + v1) + (v2 + v3)) + ((v4 + v5) + (v6 + v7));
    }
    for (; i < end; i++) acc += __half2float(g_s2h[(size_t)g_rows[i] * 32 + lane]);
    g_z2[(size_t)w * 32 + lane] = fmaf(g_dinv[w], acc, b2[lane]);
}

// ---------------- decode: out[p] = dot(z2[a], z2[b]) over 32 dims ----------------
__global__ __launch_bounds__(256) void k_decode(const void* __restrict__ eli,
                                                float* __restrict__ out, int EL) {
    int t = blockIdx.x * blockDim.x + threadIdx.x;
    int p = t >> 3;
    int j = t & 7;
    if (p >= EL) return;
    int is32 = g_is32;
    int a = edge_at(eli, p, is32);
    int b = edge_at(eli, (long long)EL + p, is32);
    float4 va = ((const float4*)g_z2)[a * 8 + j];
    float4 vb = ((const float4*)g_z2)[b * 8 + j];
    float s = va.x * vb.x + va.y * vb.y + va.z * vb.z + va.w * vb.w;
    s += __shfl_down_sync(0xffffffffu, s, 4, 8);
    s += __shfl_down_sync(0xffffffffu, s, 2, 8);
    s += __shfl_down_sync(0xffffffffu, s, 1, 8);
    if (j == 0) out[p] = s;
}

// ---------------- launch ----------------
extern "C" void kernel_launch(void* const* d_in, const int* in_sizes, int n_in,
                              void* d_out, int out_size) {
    const float* x   = (const float*)d_in[0];
    const float* W1  = (const float*)d_in[1];
    const float* b1  = (const float*)d_in[2];
    const float* W2  = (const float*)d_in[3];
    const float* b2  = (const float*)d_in[4];
    const void*  ei  = d_in[5];
    const void*  eli = d_in[6];

    int H  = in_sizes[2];                 // 64
    int F  = in_sizes[1] / H;             // 128
    int N  = in_sizes[0] / F;             // 100000
    int E  = in_sizes[5] / 2;             // 3200000
    int EL = in_sizes[6] / 2;             // 200000
    float* out = (float*)d_out;

    int NB1024 = (N + 1023) / 1024;
    int EQ = (E + 3) / 4;                  // edge quads
    int gemm1_smem = (128 * HPAD + 64 * HPAD) * sizeof(unsigned int);   // ~51KB
    cudaFuncSetAttribute(k_gemm1, cudaFuncAttributeMaxDynamicSharedMemorySize, gemm1_smem);

    cudaStream_t s2;
    cudaStreamCreateWithFlags(&s2, cudaStreamNonBlocking);
    cudaEvent_t ev_fork, ev_scan, ev_join;
    cudaEventCreateWithFlags(&ev_fork, cudaEventDisableTiming);
    cudaEventCreateWithFlags(&ev_scan, cudaEventDisableTiming);
    cudaEventCreateWithFlags(&ev_join, cudaEventDisableTiming);

    // fork immediately: raw gemm1 depends on nothing
    cudaEventRecord(ev_fork, 0);
    cudaStreamWaitEvent(s2, ev_fork, 0);
    k_gemm1<<<(N + 127) / 128, 256, gemm1_smem, s2>>>(x, W1, N);

    // CSR build on main stream
    k_prep<<<(N + 255) / 256, 256>>>(ei, E, N);
    k_count<<<(EQ + 255) / 256, 256>>>(ei, E);
    k_scan<<<NB1024, 1024>>>(N, E);
    cudaEventRecord(ev_scan, 0);

    // side stream: scale s1h by dinv once scan is done (overlaps with fill)
    cudaStreamWaitEvent(s2, ev_scan, 0);
    k_scale1<<<(N * 4 + 255) / 256, 256, 0, s2>>>(N);
    cudaEventRecord(ev_join, s2);

    k_fill<<<(EQ + 255) / 256, 256>>>(ei, E);
    cudaStreamWaitEvent(0, ev_join, 0);

    // layer 1 aggregation, layer 2 gemm + aggregation
    k_agg1<<<(N + 7) / 8, 256>>>(b1, N);
    k_gemm2<<<(N + 63) / 64, 256>>>(W2, N);
    k_agg2<<<(N + 7) / 8, 256>>>(b2, N);

    // link decode
    k_decode<<<(EL * 8 + 255) / 256, 256>>>(eli, out, EL);

    cudaEventDestroy(ev_fork);
    cudaEventDestroy(ev_scan);
    cudaEventDestroy(ev_join);
    cudaStreamDestroy(s2);
}

// round 8
// speedup vs baseline: 1.3595x; 1.0898x over previous
#include <cuda_runtime.h>
#include <cuda_fp16.h>

// ---------------- fixed problem capacities (dataset is fixed) ----------------
#define NMAX 100000
#define EMAX 3200000
#define HDIM 64
#define ODIM 32
#define FDIM 128
#define XSTR 65    // padded fp32 [k][n] stride (gemm2)
#define HPAD 68    // padded half2/uint stride (=136 halves) for tensor gemm smem

// ---------------- device scratch (no allocations allowed) ----------------
__device__ int   g_is32;                              // 1 if edge indices are int32
__device__ int   g_ecnt[NMAX];                        // in-degree (no self loop)
__device__ int   g_ptr[NMAX + 1];                     // CSR offsets
__device__ int   g_cursor[NMAX];                      // fill cursors
__device__ unsigned long long g_scanstate[128];       // lookback: (flag<<32)|sum
__device__ float g_dinv[NMAX];                        // 1/sqrt(deg+1)
__device__ __align__(16) int     g_rows[EMAX];        // CSR adjacency: src per slot
__device__ __align__(16) __half2 g_s1h[NMAX * 32];    // fp16 dinv*(x@W1): 64 vals/node
__device__ __align__(16) float   g_z1[NMAX * HDIM];   // relu layer-1 output (fp32)
__device__ __align__(16) __half  g_s2h[NMAX * ODIM];  // fp16 dinv*(z1@W2): 32 vals/node
__device__ __align__(16) float   g_z2[NMAX * ODIM];   // layer-2 output (fp32)

__device__ __forceinline__ int edge_at(const void* p, long long j, int is32) {
    if (is32) return ((const int*)p)[j];
    return (int)((const long long*)p)[j];
}
__device__ __forceinline__ unsigned int pack_h2(float a, float b) {
    __half2 h = __floats2half2_rn(a, b);
    return *reinterpret_cast<unsigned int*>(&h);
}

// ---------------- prep: dtype detect + zero counters/flags ----------------
__global__ void k_prep(const void* ei, int E, int N) {
    int i = blockIdx.x * blockDim.x + threadIdx.x;
    if (i < N) g_ecnt[i] = 0;
    if (i < 128) g_scanstate[i] = 0ull;
    if (blockIdx.x == 0) {
        __shared__ int bad;
        if (threadIdx.x == 0) bad = 0;
        __syncthreads();
        int n = (2 * E < 256) ? 2 * E : 256;
        if (threadIdx.x < n) {
            long long v = ((const long long*)ei)[threadIdx.x];
            if (v < 0 || v >= NMAX) atomicOr(&bad, 1);
        }
        __syncthreads();
        if (threadIdx.x == 0) g_is32 = bad;
    }
}

// ---------------- count: 4 edges per thread, vectorized loads ----------------
__global__ void k_count(const void* __restrict__ ei, int E) {
    int q = blockIdx.x * blockDim.x + threadIdx.x;
    int e0 = q * 4;
    if (e0 >= E) return;
    int is32 = g_is32;
    if (e0 + 4 <= E) {
        if (is32) {
            int4 c = *(const int4*)((const int*)ei + E + e0);
            atomicAdd(&g_ecnt[c.x], 1);
            atomicAdd(&g_ecnt[c.y], 1);
            atomicAdd(&g_ecnt[c.z], 1);
            atomicAdd(&g_ecnt[c.w], 1);
        } else {
            const longlong2* p = (const longlong2*)((const long long*)ei + E + e0);
            longlong2 a = p[0], b = p[1];
            atomicAdd(&g_ecnt[(int)a.x], 1);
            atomicAdd(&g_ecnt[(int)a.y], 1);
            atomicAdd(&g_ecnt[(int)b.x], 1);
            atomicAdd(&g_ecnt[(int)b.y], 1);
        }
    } else {
        for (int e = e0; e < E; e++)
            atomicAdd(&g_ecnt[edge_at(ei, (long long)E + e, is32)], 1);
    }
}

// ---- single-pass exclusive scan (warp-shuffle + decoupled lookback) ----
__global__ void k_scan(int N, int E) {
    __shared__ int wsum[32];
    __shared__ int s_prefix;
    int t = threadIdx.x, b = blockIdx.x;
    int lane = t & 31, wid = t >> 5;
    int i = b * 1024 + t;
    int v = (i < N) ? g_ecnt[i] : 0;

    // warp inclusive scan
    int s = v;
#pragma unroll
    for (int o = 1; o < 32; o <<= 1) {
        int y = __shfl_up_sync(0xffffffffu, s, o);
        if (lane >= o) s += y;
    }
    if (lane == 31) wsum[wid] = s;
    __syncthreads();
    if (wid == 0) {
        int ws = wsum[lane];
#pragma unroll
        for (int o = 1; o < 32; o <<= 1) {
            int y = __shfl_up_sync(0xffffffffu, ws, o);
            if (lane >= o) ws += y;
        }
        wsum[lane] = ws;
    }
    __syncthreads();
    int incl = s + (wid ? wsum[wid - 1] : 0);   // block-inclusive
    int btotal = wsum[31];

    if (t == 0) {
        unsigned long long total = (unsigned long long)(unsigned int)btotal;
        if (b == 0) {
            atomicExch(&g_scanstate[0], (2ull << 32) | total);
            s_prefix = 0;
        } else {
            atomicExch(&g_scanstate[b], (1ull << 32) | total);
            long long pref = 0;
            for (int j = b - 1; j >= 0;) {
                unsigned long long st;
                do { st = atomicAdd(&g_scanstate[j], 0ull); } while ((st >> 32) == 0);
                if ((st >> 32) == 2ull) { pref += (long long)(st & 0xffffffffull); break; }
                pref += (long long)(st & 0xffffffffull);
                j--;
            }
            atomicExch(&g_scanstate[b],
                       (2ull << 32) | (unsigned long long)(unsigned int)(pref + (long long)btotal));
            s_prefix = (int)pref;
        }
    }
    __syncthreads();
    int p = s_prefix + incl - v;
    if (i < N) {
        g_ptr[i] = p;
        g_cursor[i] = p;
        g_dinv[i] = rsqrtf((float)(g_ecnt[i] + 1));
    }
    if (i == 0) g_ptr[N] = E;
}

// ---------------- fill: 4 edges per thread, vectorized loads ----------------
__global__ void k_fill(const void* __restrict__ ei, int E) {
    int q = blockIdx.x * blockDim.x + threadIdx.x;
    int e0 = q * 4;
    if (e0 >= E) return;
    int is32 = g_is32;
    if (e0 + 4 <= E) {
        int4 r, c;
        if (is32) {
            r = *(const int4*)((const int*)ei + e0);
            c = *(const int4*)((const int*)ei + E + e0);
        } else {
            const longlong2* rp = (const longlong2*)((const long long*)ei + e0);
            const longlong2* cp = (const longlong2*)((const long long*)ei + E + e0);
            longlong2 ra = rp[0], rb = rp[1], ca = cp[0], cb = cp[1];
            r = make_int4((int)ra.x, (int)ra.y, (int)rb.x, (int)rb.y);
            c = make_int4((int)ca.x, (int)ca.y, (int)cb.x, (int)cb.y);
        }
        g_rows[atomicAdd(&g_cursor[c.x], 1)] = r.x;
        g_rows[atomicAdd(&g_cursor[c.y], 1)] = r.y;
        g_rows[atomicAdd(&g_cursor[c.z], 1)] = r.z;
        g_rows[atomicAdd(&g_cursor[c.w], 1)] = r.w;
    } else {
        for (int e = e0; e < E; e++) {
            int rr = edge_at(ei, e, is32);
            int cc = edge_at(ei, (long long)E + e, is32);
            g_rows[atomicAdd(&g_cursor[cc], 1)] = rr;
        }
    }
}

// ---------------- GEMM1 (tensor cores): s1h_raw = fp16( x @ W1 ) ----------------
__global__ __launch_bounds__(256) void k_gemm1(const float* __restrict__ x,
                                               const float* __restrict__ W1, int N) {
    extern __shared__ unsigned int smu[];
    unsigned int* xh = smu;                 // [128][HPAD] uints (half2)
    unsigned int* wh = smu + 128 * HPAD;    // [64][HPAD]  uints: W1 transposed [n][k]
    __half* whh = (__half*)wh;
    int t = threadIdx.x;

    for (int i = t; i < FDIM * HDIM; i += 256) {
        int k = i >> 6, n = i & 63;
        whh[n * (2 * HPAD) + k] = __float2half_rn(W1[i]);
    }
    int node0 = blockIdx.x * 128;
    const float4* x4 = (const float4*)x;
    for (int i = t; i < 128 * 32; i += 256) {
        int nd = i >> 5, kq = i & 31;
        int gn = node0 + nd;
        float4 v = (gn < N) ? x4[(size_t)gn * 32 + kq] : make_float4(0.f, 0.f, 0.f, 0.f);
        xh[nd * HPAD + kq * 2]     = pack_h2(v.x, v.y);
        xh[nd * HPAD + kq * 2 + 1] = pack_h2(v.z, v.w);
    }
    __syncthreads();

    int wid = t >> 5, lane = t & 31;
    int g = lane >> 2, tq = lane & 3;
    int nodeW = wid * 16;

    unsigned int A[8][4];
#pragma unroll
    for (int ks = 0; ks < 8; ks++) {
        int base0 = (nodeW + g) * HPAD + ks * 8 + tq;
        int base1 = (nodeW + g + 8) * HPAD + ks * 8 + tq;
        A[ks][0] = xh[base0];
        A[ks][1] = xh[base1];
        A[ks][2] = xh[base0 + 4];
        A[ks][3] = xh[base1 + 4];
    }

    float acc[8][4];
#pragma unroll
    for (int nt = 0; nt < 8; nt++)
#pragma unroll
        for (int j = 0; j < 4; j++) acc[nt][j] = 0.f;

#pragma unroll
    for (int nt = 0; nt < 8; nt++) {
        int brow = (nt * 8 + g) * HPAD + tq;
#pragma unroll
        for (int ks = 0; ks < 8; ks++) {
            unsigned int b0 = wh[brow + ks * 8];
            unsigned int b1 = wh[brow + ks * 8 + 4];
            asm volatile(
                "mma.sync.aligned.m16n8k16.row.col.f32.f16.f16.f32 "
                "{%0,%1,%2,%3}, {%4,%5,%6,%7}, {%8,%9}, {%0,%1,%2,%3};"
                : "+f"(acc[nt][0]), "+f"(acc[nt][1]), "+f"(acc[nt][2]), "+f"(acc[nt][3])
                : "r"(A[ks][0]), "r"(A[ks][1]), "r"(A[ks][2]), "r"(A[ks][3]),
                  "r"(b0), "r"(b1));
        }
    }

    int gn0 = node0 + nodeW + g;
    int gn1 = gn0 + 8;
    unsigned int* s1u = (unsigned int*)g_s1h;
#pragma unroll
    for (int nt = 0; nt < 8; nt++) {
        int ch = (nt * 8 + tq * 2) >> 1;
        if (gn0 < N) s1u[(size_t)gn0 * 32 + ch] = pack_h2(acc[nt][0], acc[nt][1]);
        if (gn1 < N) s1u[(size_t)gn1 * 32 + ch] = pack_h2(acc[nt][2], acc[nt][3]);
    }
}

// ---------------- scale1: s1h *= dinv ----------------
__global__ void k_scale1(int N) {
    int tid = blockIdx.x * blockDim.x + threadIdx.x;
    int node = tid >> 2, q = tid & 3;
    if (node >= N) return;
    float d = g_dinv[node];
    uint4* p = (uint4*)g_s1h + (size_t)node * 8 + q * 2;
#pragma unroll
    for (int u = 0; u < 2; u++) {
        uint4 v = p[u];
        unsigned int* vi = (unsigned int*)&v;
#pragma unroll
        for (int j = 0; j < 4; j++) {
            float2 f = __half22float2(*(__half2*)&vi[j]);
            vi[j] = pack_h2(d * f.x, d * f.y);
        }
        p[u] = v;
    }
}

// ---- agg1: z1 = relu(dinv*(sum_nbrs s1h + self) + b1). 2 edges/warp-step ----
// 16 lanes x uint2(8B) cover one 128B row; sub=lane>>4 picks edge parity.
__global__ __launch_bounds__(256) void k_agg1(const float* __restrict__ b1, int N) {
    int w = (blockIdx.x * blockDim.x + threadIdx.x) >> 5;
    int lane = threadIdx.x & 31;
    if (w >= N) return;
    int h = lane & 15, sub = lane >> 4;
    int beg = g_ptr[w], end = g_ptr[w + 1];
    const uint2* s1 = (const uint2*)g_s1h;     // 16 uint2 per row

    float a0 = 0.f, a1 = 0.f, a2 = 0.f, a3 = 0.f;
    int nE = end - beg;
    int nChunk = nE >> 3;                       // full 8-edge chunks
    for (int c = 0; c < nChunk; c++) {
        int base = beg + c * 8 + sub;
        int r0 = g_rows[base], r1 = g_rows[base + 2];
        int r2 = g_rows[base + 4], r3 = g_rows[base + 6];
        uint2 u0 = s1[(size_t)r0 * 16 + h];
        uint2 u1 = s1[(size_t)r1 * 16 + h];
        uint2 u2 = s1[(size_t)r2 * 16 + h];
        uint2 u3 = s1[(size_t)r3 * 16 + h];
        float2 f;
        f = __half22float2(*(__half2*)&u0.x); a0 += f.x; a1 += f.y;
        f = __half22float2(*(__half2*)&u0.y); a2 += f.x; a3 += f.y;
        f = __half22float2(*(__half2*)&u1.x); a0 += f.x; a1 += f.y;
        f = __half22float2(*(__half2*)&u1.y); a2 += f.x; a3 += f.y;
        f = __half22float2(*(__half2*)&u2.x); a0 += f.x; a1 += f.y;
        f = __half22float2(*(__half2*)&u2.y); a2 += f.x; a3 += f.y;
        f = __half22float2(*(__half2*)&u3.x); a0 += f.x; a1 += f.y;
        f = __half22float2(*(__half2*)&u3.y); a2 += f.x; a3 += f.y;
    }
    for (int i = beg + nChunk * 8 + sub; i < end; i += 2) {
        int r = g_rows[i];
        uint2 u = s1[(size_t)r * 16 + h];
        float2 f;
        f = __half22float2(*(__half2*)&u.x); a0 += f.x; a1 += f.y;
        f = __half22float2(*(__half2*)&u.y); a2 += f.x; a3 += f.y;
    }
    // combine the two edge-parity halves
    a0 += __shfl_xor_sync(0xffffffffu, a0, 16);
    a1 += __shfl_xor_sync(0xffffffffu, a1, 16);
    a2 += __shfl_xor_sync(0xffffffffu, a2, 16);
    a3 += __shfl_xor_sync(0xffffffffu, a3, 16);

    if (sub == 0) {
        uint2 us = s1[(size_t)w * 16 + h];      // self
        float2 f;
        f = __half22float2(*(__half2*)&us.x); a0 += f.x; a1 += f.y;
        f = __half22float2(*(__half2*)&us.y); a2 += f.x; a3 += f.y;
        float d = g_dinv[w];
        float4 bb = ((const float4*)b1)[h];
        float4 z;
        z.x = fmaxf(fmaf(d, a0, bb.x), 0.f);
        z.y = fmaxf(fmaf(d, a1, bb.y), 0.f);
        z.z = fmaxf(fmaf(d, a2, bb.z), 0.f);
        z.w = fmaxf(fmaf(d, a3, bb.w), 0.f);
        ((float4*)g_z1)[(size_t)w * 16 + h] = z;
    }
}

// ---------------- GEMM2: s2h = fp16( dinv * (z1 @ W2) )   [N,64]x[64,32] ----------------
__global__ __launch_bounds__(256) void k_gemm2(const float* __restrict__ W2, int N) {
    __shared__ float Ws[HDIM * ODIM];
    __shared__ float zs[HDIM * XSTR];
    int t = threadIdx.x;
    for (int i = t; i < HDIM * ODIM; i += 256) Ws[i] = W2[i];

    int node0 = blockIdx.x * 64;
    int lane = t & 31, wrp = t >> 5;
#pragma unroll
    for (int rep = 0; rep < 16; rep++) {
        int n = wrp * 8 + (rep >> 1);
        int k = (rep & 1) * 32 + lane;
        int gn = node0 + n;
        float v = (gn < N) ? g_z1[(size_t)gn * HDIM + k] : 0.f;
        zs[k * XSTR + n] = v;
    }
    __syncthreads();

    int n = t & 63;
    int og = t >> 6;
    float acc[8];
#pragma unroll
    for (int i = 0; i < 8; i++) acc[i] = 0.f;
    const float4* Ws4 = (const float4*)Ws;
#pragma unroll 4
    for (int k = 0; k < HDIM; k++) {
        float xv = zs[k * XSTR + n];
        float4 w0 = Ws4[k * 8 + og * 2];
        float4 w1 = Ws4[k * 8 + og * 2 + 1];
        acc[0] = fmaf(xv, w0.x, acc[0]); acc[1] = fmaf(xv, w0.y, acc[1]);
        acc[2] = fmaf(xv, w0.z, acc[2]); acc[3] = fmaf(xv, w0.w, acc[3]);
        acc[4] = fmaf(xv, w1.x, acc[4]); acc[5] = fmaf(xv, w1.y, acc[5]);
        acc[6] = fmaf(xv, w1.z, acc[6]); acc[7] = fmaf(xv, w1.w, acc[7]);
    }
    int gn = node0 + n;
    if (gn < N) {
        float d = g_dinv[gn];
        unsigned int p[4];
#pragma unroll
        for (int j = 0; j < 4; j++) p[j] = pack_h2(d * acc[2 * j], d * acc[2 * j + 1]);
        *(uint4*)(g_s2h + (size_t)gn * ODIM + og * 8) = make_uint4(p[0], p[1], p[2], p[3]);
    }
}

// ---- agg2: z2 = dinv*(sum + self) + b2. 2 edges/warp-step, uint loads ----
__global__ __launch_bounds__(256) void k_agg2(const float* __restrict__ b2, int N) {
    int w = (blockIdx.x * blockDim.x + threadIdx.x) >> 5;
    int lane = threadIdx.x & 31;
    if (w >= N) return;
    int h = lane & 15, sub = lane >> 4;
    int beg = g_ptr[w], end = g_ptr[w + 1];
    const unsigned int* s2 = (const unsigned int*)g_s2h;   // 16 uints per row

    float a0 = 0.f, a1 = 0.f;
    int nE = end - beg;
    int nChunk = nE >> 3;
    for (int c = 0; c < nChunk; c++) {
        int base = beg + c * 8 + sub;
        int r0 = g_rows[base], r1 = g_rows[base + 2];
        int r2 = g_rows[base + 4], r3 = g_rows[base + 6];
        unsigned int u0 = s2[(size_t)r0 * 16 + h];
        unsigned int u1 = s2[(size_t)r1 * 16 + h];
        unsigned int u2 = s2[(size_t)r2 * 16 + h];
        unsigned int u3 = s2[(size_t)r3 * 16 + h];
        float2 f;
        f = __half22float2(*(__half2*)&u0); a0 += f.x; a1 += f.y;
        f = __half22float2(*(__half2*)&u1); a0 += f.x; a1 += f.y;
        f = __half22float2(*(__half2*)&u2); a0 += f.x; a1 += f.y;
        f = __half22float2(*(__half2*)&u3); a0 += f.x; a1 += f.y;
    }
    for (int i = beg + nChunk * 8 + sub; i < end; i += 2) {
        unsigned int u = s2[(size_t)g_rows[i] * 16 + h];
        float2 f = __half22float2(*(__half2*)&u);
        a0 += f.x; a1 += f.y;
    }
    a0 += __shfl_xor_sync(0xffffffffu, a0, 16);
    a1 += __shfl_xor_sync(0xffffffffu, a1, 16);

    if (sub == 0) {
        unsigned int us = s2[(size_t)w * 16 + h];
        float2 f = __half22float2(*(__half2*)&us);
        a0 += f.x; a1 += f.y;
        float d = g_dinv[w];
        float2 bb = ((const float2*)b2)[h];
        ((float2*)g_z2)[(size_t)w * 16 + h] =
            make_float2(fmaf(d, a0, bb.x), fmaf(d, a1, bb.y));
    }
}

// ---------------- decode: out[p] = dot(z2[a], z2[b]) over 32 dims ----------------
__global__ __launch_bounds__(256) void k_decode(const void* __restrict__ eli,
                                                float* __restrict__ out, int EL) {
    int t = blockIdx.x * blockDim.x + threadIdx.x;
    int p = t >> 3;
    int j = t & 7;
    if (p >= EL) return;
    int is32 = g_is32;
    int a = edge_at(eli, p, is32);
    int b = edge_at(eli, (long long)EL + p, is32);
    float4 va = ((const float4*)g_z2)[a * 8 + j];
    float4 vb = ((const float4*)g_z2)[b * 8 + j];
    float s = va.x * vb.x + va.y * vb.y + va.z * vb.z + va.w * vb.w;
    s += __shfl_down_sync(0xffffffffu, s, 4, 8);
    s += __shfl_down_sync(0xffffffffu, s, 2, 8);
    s += __shfl_down_sync(0xffffffffu, s, 1, 8);
    if (j == 0) out[p] = s;
}

// ---------------- launch ----------------
extern "C" void kernel_launch(void* const* d_in, const int* in_sizes, int n_in,
                              void* d_out, int out_size) {
    const float* x   = (const float*)d_in[0];
    const float* W1  = (const float*)d_in[1];
    const float* b1  = (const float*)d_in[2];
    const float* W2  = (const float*)d_in[3];
    const float* b2  = (const float*)d_in[4];
    const void*  ei  = d_in[5];
    const void*  eli = d_in[6];

    int H  = in_sizes[2];                 // 64
    int F  = in_sizes[1] / H;             // 128
    int N  = in_sizes[0] / F;             // 100000
    int E  = in_sizes[5] / 2;             // 3200000
    int EL = in_sizes[6] / 2;             // 200000
    float* out = (float*)d_out;

    int NB1024 = (N + 1023) / 1024;
    int EQ = (E + 3) / 4;
    int gemm1_smem = (128 * HPAD + 64 * HPAD) * sizeof(unsigned int);   // ~51KB
    cudaFuncSetAttribute(k_gemm1, cudaFuncAttributeMaxDynamicSharedMemorySize, gemm1_smem);

    cudaStream_t s2;
    cudaStreamCreateWithFlags(&s2, cudaStreamNonBlocking);
    cudaEvent_t ev_fork, ev_scan, ev_join;
    cudaEventCreateWithFlags(&ev_fork, cudaEventDisableTiming);
    cudaEventCreateWithFlags(&ev_scan, cudaEventDisableTiming);
    cudaEventCreateWithFlags(&ev_join, cudaEventDisableTiming);

    // fork immediately: raw gemm1 depends on nothing
    cudaEventRecord(ev_fork, 0);
    cudaStreamWaitEvent(s2, ev_fork, 0);
    k_gemm1<<<(N + 127) / 128, 256, gemm1_smem, s2>>>(x, W1, N);

    // CSR build on main stream
    k_prep<<<(N + 255) / 256, 256>>>(ei, E, N);
    k_count<<<(EQ + 255) / 256, 256>>>(ei, E);
    k_scan<<<NB1024, 1024>>>(N, E);
    cudaEventRecord(ev_scan, 0);

    // side stream: scale s1h by dinv once scan is done (overlaps with fill)
    cudaStreamWaitEvent(s2, ev_scan, 0);
    k_scale1<<<(N * 4 + 255) / 256, 256, 0, s2>>>(N);
    cudaEventRecord(ev_join, s2);

    k_fill<<<(EQ + 255) / 256, 256>>>(ei, E);
    cudaStreamWaitEvent(0, ev_join, 0);

    // layer 1 aggregation, layer 2 gemm + aggregation
    k_agg1<<<(N + 7) / 8, 256>>>(b1, N);
    k_gemm2<<<(N + 63) / 64, 256>>>(W2, N);
    k_agg2<<<(N + 7) / 8, 256>>>(b2, N);

    // link decode
    k_decode<<<(EL * 8 + 255) / 256, 256>>>(eli, out, EL);

    cudaEventDestroy(ev_fork);
    cudaEventDestroy(ev_scan);
    cudaEventDestroy(ev_join);
    cudaStreamDestroy(s2);
}

// round 9
// speedup vs baseline: 1.3735x; 1.0103x over previous
#include <cuda_runtime.h>
#include <cuda_fp16.h>

// ---------------- fixed problem capacities (dataset is fixed) ----------------
#define NMAX 100000
#define EMAX 3200000
#define HDIM 64
#define ODIM 32
#define FDIM 128
#define XSTR 65    // padded fp32 [k][n] stride (gemm2)
#define HPAD 68    // padded half2/uint stride (=136 halves) for tensor gemm smem

// ---------------- device scratch (no allocations allowed) ----------------
__device__ int   g_is32;                              // 1 if edge indices are int32
__device__ int   g_ecnt[NMAX];                        // in-degree (no self loop)
__device__ int   g_ptr[NMAX + 1];                     // CSR offsets
__device__ unsigned long long g_scanstate[128];       // lookback: (flag<<32)|sum
__device__ float g_dinv[NMAX];                        // 1/sqrt(deg+1)
__device__ __align__(16) int     g_rank[EMAX];        // per-edge rank within dst
__device__ __align__(16) int     g_rows[EMAX];        // CSR adjacency: src per slot
__device__ __align__(16) __half2 g_s1h[NMAX * 32];    // fp16 dinv*(x@W1): 64 vals/node
__device__ __align__(16) float   g_z1[NMAX * HDIM];   // relu layer-1 output (fp32)
__device__ __align__(16) __half  g_s2h[NMAX * ODIM];  // fp16 dinv*(z1@W2): 32 vals/node
__device__ __align__(16) float   g_z2[NMAX * ODIM];   // layer-2 output (fp32)

__device__ __forceinline__ int edge_at(const void* p, long long j, int is32) {
    if (is32) return ((const int*)p)[j];
    return (int)((const long long*)p)[j];
}
__device__ __forceinline__ unsigned int pack_h2(float a, float b) {
    __half2 h = __floats2half2_rn(a, b);
    return *reinterpret_cast<unsigned int*>(&h);
}

// ---------------- prep: dtype detect + zero counters/flags ----------------
__global__ void k_prep(const void* ei, int E, int N) {
    int i = blockIdx.x * blockDim.x + threadIdx.x;
    if (i < N) g_ecnt[i] = 0;
    if (i < 128) g_scanstate[i] = 0ull;
    if (blockIdx.x == 0) {
        __shared__ int bad;
        if (threadIdx.x == 0) bad = 0;
        __syncthreads();
        int n = (2 * E < 256) ? 2 * E : 256;
        if (threadIdx.x < n) {
            long long v = ((const long long*)ei)[threadIdx.x];
            if (v < 0 || v >= NMAX) atomicOr(&bad, 1);
        }
        __syncthreads();
        if (threadIdx.x == 0) g_is32 = bad;
    }
}

// ------- count: 4 edges/thread; also records per-edge rank within its dst -------
__global__ void k_count(const void* __restrict__ ei, int E) {
    int q = blockIdx.x * blockDim.x + threadIdx.x;
    int e0 = q * 4;
    if (e0 >= E) return;
    int is32 = g_is32;
    if (e0 + 4 <= E) {
        int4 c;
        if (is32) {
            c = *(const int4*)((const int*)ei + E + e0);
        } else {
            const longlong2* p = (const longlong2*)((const long long*)ei + E + e0);
            longlong2 a = p[0], b = p[1];
            c = make_int4((int)a.x, (int)a.y, (int)b.x, (int)b.y);
        }
        int4 rk;
        rk.x = atomicAdd(&g_ecnt[c.x], 1);
        rk.y = atomicAdd(&g_ecnt[c.y], 1);
        rk.z = atomicAdd(&g_ecnt[c.z], 1);
        rk.w = atomicAdd(&g_ecnt[c.w], 1);
        *(int4*)(g_rank + e0) = rk;
    } else {
        for (int e = e0; e < E; e++) {
            int cc = edge_at(ei, (long long)E + e, is32);
            g_rank[e] = atomicAdd(&g_ecnt[cc], 1);
        }
    }
}

// ---- single-pass exclusive scan: warp scan + WARP-PARALLEL decoupled lookback ----
__global__ void k_scan(int N, int E) {
    __shared__ int wsum[32];
    __shared__ int s_prefix;
    int t = threadIdx.x, b = blockIdx.x;
    int lane = t & 31, wid = t >> 5;
    int i = b * 1024 + t;
    int v = (i < N) ? g_ecnt[i] : 0;

    int s = v;
#pragma unroll
    for (int o = 1; o < 32; o <<= 1) {
        int y = __shfl_up_sync(0xffffffffu, s, o);
        if (lane >= o) s += y;
    }
    if (lane == 31) wsum[wid] = s;
    __syncthreads();
    if (wid == 0) {
        int ws = wsum[lane];
#pragma unroll
        for (int o = 1; o < 32; o <<= 1) {
            int y = __shfl_up_sync(0xffffffffu, ws, o);
            if (lane >= o) ws += y;
        }
        wsum[lane] = ws;
    }
    __syncthreads();
    int incl = s + (wid ? wsum[wid - 1] : 0);
    int btotal = wsum[31];

    if (wid == 0) {
        if (b == 0) {
            if (lane == 0) {
                atomicExch(&g_scanstate[0], (2ull << 32) | (unsigned int)btotal);
                s_prefix = 0;
            }
        } else {
            if (lane == 0)
                atomicExch(&g_scanstate[b], (1ull << 32) | (unsigned int)btotal);
            __syncwarp();
            long long pref = 0;
            int base = b;
            while (true) {
                int idx = base - 32 + lane;
                bool valid = idx >= 0;
                unsigned long long st = 0;
                if (valid) {
                    do { st = atomicAdd(&g_scanstate[idx], 0ull); } while ((st >> 32) == 0);
                }
                unsigned m = __ballot_sync(0xffffffffu, valid && (st >> 32) == 2ull);
                int cut = m ? (31 - __clz(m)) : 32;       // nearest inclusive-prefix lane
                bool contrib = valid && (cut == 32 || lane >= cut);
                long long c = contrib ? (long long)(st & 0xffffffffull) : 0;
#pragma unroll
                for (int o = 16; o; o >>= 1) c += __shfl_xor_sync(0xffffffffu, c, o);
                pref += c;
                if (cut != 32) break;
                base -= 32;
            }
            if (lane == 0) {
                atomicExch(&g_scanstate[b],
                           (2ull << 32) | (unsigned int)(pref + (long long)btotal));
                s_prefix = (int)pref;
            }
        }
    }
    __syncthreads();
    int p = s_prefix + incl - v;
    if (i < N) {
        g_ptr[i] = p;
        g_dinv[i] = rsqrtf((float)(g_ecnt[i] + 1));
    }
    if (i == 0) g_ptr[N] = E;
}

// ------- scatter (atomic-free fill): g_rows[ptr[c]+rank] = r -------
__global__ void k_scatter(const void* __restrict__ ei, int E) {
    int q = blockIdx.x * blockDim.x + threadIdx.x;
    int e0 = q * 4;
    if (e0 >= E) return;
    int is32 = g_is32;
    if (e0 + 4 <= E) {
        int4 r, c;
        if (is32) {
            r = *(const int4*)((const int*)ei + e0);
            c = *(const int4*)((const int*)ei + E + e0);
        } else {
            const longlong2* rp = (const longlong2*)((const long long*)ei + e0);
            const longlong2* cp = (const longlong2*)((const long long*)ei + E + e0);
            longlong2 ra = rp[0], rb = rp[1], ca = cp[0], cb = cp[1];
            r = make_int4((int)ra.x, (int)ra.y, (int)rb.x, (int)rb.y);
            c = make_int4((int)ca.x, (int)ca.y, (int)cb.x, (int)cb.y);
        }
        int4 rk = *(const int4*)(g_rank + e0);
        g_rows[g_ptr[c.x] + rk.x] = r.x;
        g_rows[g_ptr[c.y] + rk.y] = r.y;
        g_rows[g_ptr[c.z] + rk.z] = r.z;
        g_rows[g_ptr[c.w] + rk.w] = r.w;
    } else {
        for (int e = e0; e < E; e++) {
            int rr = edge_at(ei, e, is32);
            int cc = edge_at(ei, (long long)E + e, is32);
            g_rows[g_ptr[cc] + g_rank[e]] = rr;
        }
    }
}

// ---------------- GEMM1 (tensor cores): s1h_raw = fp16( x @ W1 ) ----------------
__global__ __launch_bounds__(256) void k_gemm1(const float* __restrict__ x,
                                               const float* __restrict__ W1, int N) {
    extern __shared__ unsigned int smu[];
    unsigned int* xh = smu;                 // [128][HPAD] uints (half2)
    unsigned int* wh = smu + 128 * HPAD;    // [64][HPAD]  uints: W1 transposed [n][k]
    __half* whh = (__half*)wh;
    int t = threadIdx.x;

    for (int i = t; i < FDIM * HDIM; i += 256) {
        int k = i >> 6, n = i & 63;
        whh[n * (2 * HPAD) + k] = __float2half_rn(W1[i]);
    }
    int node0 = blockIdx.x * 128;
    const float4* x4 = (const float4*)x;
    for (int i = t; i < 128 * 32; i += 256) {
        int nd = i >> 5, kq = i & 31;
        int gn = node0 + nd;
        float4 v = (gn < N) ? x4[(size_t)gn * 32 + kq] : make_float4(0.f, 0.f, 0.f, 0.f);
        xh[nd * HPAD + kq * 2]     = pack_h2(v.x, v.y);
        xh[nd * HPAD + kq * 2 + 1] = pack_h2(v.z, v.w);
    }
    __syncthreads();

    int wid = t >> 5, lane = t & 31;
    int g = lane >> 2, tq = lane & 3;
    int nodeW = wid * 16;

    unsigned int A[8][4];
#pragma unroll
    for (int ks = 0; ks < 8; ks++) {
        int base0 = (nodeW + g) * HPAD + ks * 8 + tq;
        int base1 = (nodeW + g + 8) * HPAD + ks * 8 + tq;
        A[ks][0] = xh[base0];
        A[ks][1] = xh[base1];
        A[ks][2] = xh[base0 + 4];
        A[ks][3] = xh[base1 + 4];
    }

    float acc[8][4];
#pragma unroll
    for (int nt = 0; nt < 8; nt++)
#pragma unroll
        for (int j = 0; j < 4; j++) acc[nt][j] = 0.f;

#pragma unroll
    for (int nt = 0; nt < 8; nt++) {
        int brow = (nt * 8 + g) * HPAD + tq;
#pragma unroll
        for (int ks = 0; ks < 8; ks++) {
            unsigned int b0 = wh[brow + ks * 8];
            unsigned int b1 = wh[brow + ks * 8 + 4];
            asm volatile(
                "mma.sync.aligned.m16n8k16.row.col.f32.f16.f16.f32 "
                "{%0,%1,%2,%3}, {%4,%5,%6,%7}, {%8,%9}, {%0,%1,%2,%3};"
                : "+f"(acc[nt][0]), "+f"(acc[nt][1]), "+f"(acc[nt][2]), "+f"(acc[nt][3])
                : "r"(A[ks][0]), "r"(A[ks][1]), "r"(A[ks][2]), "r"(A[ks][3]),
                  "r"(b0), "r"(b1));
        }
    }

    int gn0 = node0 + nodeW + g;
    int gn1 = gn0 + 8;
    unsigned int* s1u = (unsigned int*)g_s1h;
#pragma unroll
    for (int nt = 0; nt < 8; nt++) {
        int ch = (nt * 8 + tq * 2) >> 1;
        if (gn0 < N) s1u[(size_t)gn0 * 32 + ch] = pack_h2(acc[nt][0], acc[nt][1]);
        if (gn1 < N) s1u[(size_t)gn1 * 32 + ch] = pack_h2(acc[nt][2], acc[nt][3]);
    }
}

// ---------------- scale1: s1h *= dinv ----------------
__global__ void k_scale1(int N) {
    int tid = blockIdx.x * blockDim.x + threadIdx.x;
    int node = tid >> 2, q = tid & 3;
    if (node >= N) return;
    float d = g_dinv[node];
    uint4* p = (uint4*)g_s1h + (size_t)node * 8 + q * 2;
#pragma unroll
    for (int u = 0; u < 2; u++) {
        uint4 v = p[u];
        unsigned int* vi = (unsigned int*)&v;
#pragma unroll
        for (int j = 0; j < 4; j++) {
            float2 f = __half22float2(*(__half2*)&vi[j]);
            vi[j] = pack_h2(d * f.x, d * f.y);
        }
        p[u] = v;
    }
}

// ---- agg1: 8 lanes x uint4(16B) per 128B row; 4 edge-parities, 16 edges/iter ----
__global__ __launch_bounds__(256) void k_agg1(const float* __restrict__ b1, int N) {
    int w = (blockIdx.x * blockDim.x + threadIdx.x) >> 5;
    int lane = threadIdx.x & 31;
    if (w >= N) return;
    int h = lane & 7, sub = lane >> 3;          // h: 16B chunk, sub: edge parity 0..3
    int beg = g_ptr[w], end = g_ptr[w + 1];
    const uint4* s1 = (const uint4*)g_s1h;      // 8 uint4 per row

    float a0 = 0.f, a1 = 0.f, a2 = 0.f, a3 = 0.f;
    float a4 = 0.f, a5 = 0.f, a6 = 0.f, a7 = 0.f;
    int nE = end - beg;
    int nChunk = nE >> 4;                        // 16-edge chunks
    for (int c = 0; c < nChunk; c++) {
        int base = beg + c * 16 + sub;
        int r0 = g_rows[base],     r1 = g_rows[base + 4];
        int r2 = g_rows[base + 8], r3 = g_rows[base + 12];
        uint4 u0 = s1[(size_t)r0 * 8 + h];
        uint4 u1 = s1[(size_t)r1 * 8 + h];
        uint4 u2 = s1[(size_t)r2 * 8 + h];
        uint4 u3 = s1[(size_t)r3 * 8 + h];
        float2 f;
        f = __half22float2(*(__half2*)&u0.x); a0 += f.x; a1 += f.y;
        f = __half22float2(*(__half2*)&u0.y); a2 += f.x; a3 += f.y;
        f = __half22float2(*(__half2*)&u0.z); a4 += f.x; a5 += f.y;
        f = __half22float2(*(__half2*)&u0.w); a6 += f.x; a7 += f.y;
        f = __half22float2(*(__half2*)&u1.x); a0 += f.x; a1 += f.y;
        f = __half22float2(*(__half2*)&u1.y); a2 += f.x; a3 += f.y;
        f = __half22float2(*(__half2*)&u1.z); a4 += f.x; a5 += f.y;
        f = __half22float2(*(__half2*)&u1.w); a6 += f.x; a7 += f.y;
        f = __half22float2(*(__half2*)&u2.x); a0 += f.x; a1 += f.y;
        f = __half22float2(*(__half2*)&u2.y); a2 += f.x; a3 += f.y;
        f = __half22float2(*(__half2*)&u2.z); a4 += f.x; a5 += f.y;
        f = __half22float2(*(__half2*)&u2.w); a6 += f.x; a7 += f.y;
        f = __half22float2(*(__half2*)&u3.x); a0 += f.x; a1 += f.y;
        f = __half22float2(*(__half2*)&u3.y); a2 += f.x; a3 += f.y;
        f = __half22float2(*(__half2*)&u3.z); a4 += f.x; a5 += f.y;
        f = __half22float2(*(__half2*)&u3.w); a6 += f.x; a7 += f.y;
    }
    for (int i = beg + nChunk * 16 + sub; i < end; i += 4) {
        uint4 u = s1[(size_t)g_rows[i] * 8 + h];
        float2 f;
        f = __half22float2(*(__half2*)&u.x); a0 += f.x; a1 += f.y;
        f = __half22float2(*(__half2*)&u.y); a2 += f.x; a3 += f.y;
        f = __half22float2(*(__half2*)&u.z); a4 += f.x; a5 += f.y;
        f = __half22float2(*(__half2*)&u.w); a6 += f.x; a7 += f.y;
    }
    // reduce across the 4 edge-parity groups (xor 8, then 16)
#pragma unroll
    for (int o = 8; o <= 16; o <<= 1) {
        a0 += __shfl_xor_sync(0xffffffffu, a0, o);
        a1 += __shfl_xor_sync(0xffffffffu, a1, o);
        a2 += __shfl_xor_sync(0xffffffffu, a2, o);
        a3 += __shfl_xor_sync(0xffffffffu, a3, o);
        a4 += __shfl_xor_sync(0xffffffffu, a4, o);
        a5 += __shfl_xor_sync(0xffffffffu, a5, o);
        a6 += __shfl_xor_sync(0xffffffffu, a6, o);
        a7 += __shfl_xor_sync(0xffffffffu, a7, o);
    }
    if (sub == 0) {
        uint4 us = s1[(size_t)w * 8 + h];        // self
        float2 f;
        f = __half22float2(*(__half2*)&us.x); a0 += f.x; a1 += f.y;
        f = __half22float2(*(__half2*)&us.y); a2 += f.x; a3 += f.y;
        f = __half22float2(*(__half2*)&us.z); a4 += f.x; a5 += f.y;
        f = __half22float2(*(__half2*)&us.w); a6 += f.x; a7 += f.y;
        float d = g_dinv[w];
        float4 b0 = ((const float4*)b1)[h * 2];
        float4 b2v = ((const float4*)b1)[h * 2 + 1];
        float4 z0, z1v;
        z0.x = fmaxf(fmaf(d, a0, b0.x), 0.f);
        z0.y = fmaxf(fmaf(d, a1, b0.y), 0.f);
        z0.z = fmaxf(fmaf(d, a2, b0.z), 0.f);
        z0.w = fmaxf(fmaf(d, a3, b0.w), 0.f);
        z1v.x = fmaxf(fmaf(d, a4, b2v.x), 0.f);
        z1v.y = fmaxf(fmaf(d, a5, b2v.y), 0.f);
        z1v.z = fmaxf(fmaf(d, a6, b2v.z), 0.f);
        z1v.w = fmaxf(fmaf(d, a7, b2v.w), 0.f);
        ((float4*)g_z1)[(size_t)w * 16 + h * 2]     = z0;
        ((float4*)g_z1)[(size_t)w * 16 + h * 2 + 1] = z1v;
    }
}

// ---------------- GEMM2: s2h = fp16( dinv * (z1 @ W2) )   [N,64]x[64,32] ----------------
__global__ __launch_bounds__(256) void k_gemm2(const float* __restrict__ W2, int N) {
    __shared__ float Ws[HDIM * ODIM];
    __shared__ float zs[HDIM * XSTR];
    int t = threadIdx.x;
    for (int i = t; i < HDIM * ODIM; i += 256) Ws[i] = W2[i];

    int node0 = blockIdx.x * 64;
    int lane = t & 31, wrp = t >> 5;
#pragma unroll
    for (int rep = 0; rep < 16; rep++) {
        int n = wrp * 8 + (rep >> 1);
        int k = (rep & 1) * 32 + lane;
        int gn = node0 + n;
        float v = (gn < N) ? g_z1[(size_t)gn * HDIM + k] : 0.f;
        zs[k * XSTR + n] = v;
    }
    __syncthreads();

    int n = t & 63;
    int og = t >> 6;
    float acc[8];
#pragma unroll
    for (int i = 0; i < 8; i++) acc[i] = 0.f;
    const float4* Ws4 = (const float4*)Ws;
#pragma unroll 4
    for (int k = 0; k < HDIM; k++) {
        float xv = zs[k * XSTR + n];
        float4 w0 = Ws4[k * 8 + og * 2];
        float4 w1 = Ws4[k * 8 + og * 2 + 1];
        acc[0] = fmaf(xv, w0.x, acc[0]); acc[1] = fmaf(xv, w0.y, acc[1]);
        acc[2] = fmaf(xv, w0.z, acc[2]); acc[3] = fmaf(xv, w0.w, acc[3]);
        acc[4] = fmaf(xv, w1.x, acc[4]); acc[5] = fmaf(xv, w1.y, acc[5]);
        acc[6] = fmaf(xv, w1.z, acc[6]); acc[7] = fmaf(xv, w1.w, acc[7]);
    }
    int gn = node0 + n;
    if (gn < N) {
        float d = g_dinv[gn];
        unsigned int p[4];
#pragma unroll
        for (int j = 0; j < 4; j++) p[j] = pack_h2(d * acc[2 * j], d * acc[2 * j + 1]);
        *(uint4*)(g_s2h + (size_t)gn * ODIM + og * 8) = make_uint4(p[0], p[1], p[2], p[3]);
    }
}

// ---- agg2: 8 lanes x uint2(8B) per 64B row; 4 edge-parities, 16 edges/iter ----
__global__ __launch_bounds__(256) void k_agg2(const float* __restrict__ b2, int N) {
    int w = (blockIdx.x * blockDim.x + threadIdx.x) >> 5;
    int lane = threadIdx.x & 31;
    if (w >= N) return;
    int h = lane & 7, sub = lane >> 3;
    int beg = g_ptr[w], end = g_ptr[w + 1];
    const uint2* s2 = (const uint2*)g_s2h;       // 8 uint2 per row

    float a0 = 0.f, a1 = 0.f, a2 = 0.f, a3 = 0.f;
    int nE = end - beg;
    int nChunk = nE >> 4;
    for (int c = 0; c < nChunk; c++) {
        int base = beg + c * 16 + sub;
        int r0 = g_rows[base],     r1 = g_rows[base + 4];
        int r2 = g_rows[base + 8], r3 = g_rows[base + 12];
        uint2 u0 = s2[(size_t)r0 * 8 + h];
        uint2 u1 = s2[(size_t)r1 * 8 + h];
        uint2 u2 = s2[(size_t)r2 * 8 + h];
        uint2 u3 = s2[(size_t)r3 * 8 + h];
        float2 f;
        f = __half22float2(*(__half2*)&u0.x); a0 += f.x; a1 += f.y;
        f = __half22float2(*(__half2*)&u0.y); a2 += f.x; a3 += f.y;
        f = __half22float2(*(__half2*)&u1.x); a0 += f.x; a1 += f.y;
        f = __half22float2(*(__half2*)&u1.y); a2 += f.x; a3 += f.y;
        f = __half22float2(*(__half2*)&u2.x); a0 += f.x; a1 += f.y;
        f = __half22float2(*(__half2*)&u2.y); a2 += f.x; a3 += f.y;
        f = __half22float2(*(__half2*)&u3.x); a0 += f.x; a1 += f.y;
        f = __half22float2(*(__half2*)&u3.y); a2 += f.x; a3 += f.y;
    }
    for (int i = beg + nChunk * 16 + sub; i < end; i += 4) {
        uint2 u = s2[(size_t)g_rows[i] * 8 + h];
        float2 f;
        f = __half22float2(*(__half2*)&u.x); a0 += f.x; a1 += f.y;
        f = __half22float2(*(__half2*)&u.y); a2 += f.x; a3 += f.y;
    }
#pragma unroll
    for (int o = 8; o <= 16; o <<= 1) {
        a0 += __shfl_xor_sync(0xffffffffu, a0, o);
        a1 += __shfl_xor_sync(0xffffffffu, a1, o);
        a2 += __shfl_xor_sync(0xffffffffu, a2, o);
        a3 += __shfl_xor_sync(0xffffffffu, a3, o);
    }
    if (sub == 0) {
        uint2 us = s2[(size_t)w * 8 + h];
        float2 f;
        f = __half22float2(*(__half2*)&us.x); a0 += f.x; a1 += f.y;
        f = __half22float2(*(__half2*)&us.y); a2 += f.x; a3 += f.y;
        float d = g_dinv[w];
        float4 bb = ((const float4*)b2)[h];
        float4 z;
        z.x = fmaf(d, a0, bb.x);
        z.y = fmaf(d, a1, bb.y);
        z.z = fmaf(d, a2, bb.z);
        z.w = fmaf(d, a3, bb.w);
        ((float4*)g_z2)[(size_t)w * 8 + h] = z;
    }
}

// ---------------- decode: out[p] = dot(z2[a], z2[b]) over 32 dims ----------------
__global__ __launch_bounds__(256) void k_decode(const void* __restrict__ eli,
                                                float* __restrict__ out, int EL) {
    int t = blockIdx.x * blockDim.x + threadIdx.x;
    int p = t >> 3;
    int j = t & 7;
    if (p >= EL) return;
    int is32 = g_is32;
    int a = edge_at(eli, p, is32);
    int b = edge_at(eli, (long long)EL + p, is32);
    float4 va = ((const float4*)g_z2)[a * 8 + j];
    float4 vb = ((const float4*)g_z2)[b * 8 + j];
    float s = va.x * vb.x + va.y * vb.y + va.z * vb.z + va.w * vb.w;
    s += __shfl_down_sync(0xffffffffu, s, 4, 8);
    s += __shfl_down_sync(0xffffffffu, s, 2, 8);
    s += __shfl_down_sync(0xffffffffu, s, 1, 8);
    if (j == 0) out[p] = s;
}

// ---------------- launch ----------------
extern "C" void kernel_launch(void* const* d_in, const int* in_sizes, int n_in,
                              void* d_out, int out_size) {
    const float* x   = (const float*)d_in[0];
    const float* W1  = (const float*)d_in[1];
    const float* b1  = (const float*)d_in[2];
    const float* W2  = (const float*)d_in[3];
    const float* b2  = (const float*)d_in[4];
    const void*  ei  = d_in[5];
    const void*  eli = d_in[6];

    int H  = in_sizes[2];                 // 64
    int F  = in_sizes[1] / H;             // 128
    int N  = in_sizes[0] / F;             // 100000
    int E  = in_sizes[5] / 2;             // 3200000
    int EL = in_sizes[6] / 2;             // 200000
    float* out = (float*)d_out;

    int NB1024 = (N + 1023) / 1024;
    int EQ = (E + 3) / 4;
    int gemm1_smem = (128 * HPAD + 64 * HPAD) * sizeof(unsigned int);   // ~51KB
    cudaFuncSetAttribute(k_gemm1, cudaFuncAttributeMaxDynamicSharedMemorySize, gemm1_smem);

    cudaStream_t s2;
    cudaStreamCreateWithFlags(&s2, cudaStreamNonBlocking);
    cudaEvent_t ev_fork, ev_scan, ev_join;
    cudaEventCreateWithFlags(&ev_fork, cudaEventDisableTiming);
    cudaEventCreateWithFlags(&ev_scan, cudaEventDisableTiming);
    cudaEventCreateWithFlags(&ev_join, cudaEventDisableTiming);

    // fork immediately: raw gemm1 depends on nothing
    cudaEventRecord(ev_fork, 0);
    cudaStreamWaitEvent(s2, ev_fork, 0);
    k_gemm1<<<(N + 127) / 128, 256, gemm1_smem, s2>>>(x, W1, N);

    // CSR build on main stream
    k_prep<<<(N + 255) / 256, 256>>>(ei, E, N);
    k_count<<<(EQ + 255) / 256, 256>>>(ei, E);
    k_scan<<<NB1024, 1024>>>(N, E);
    cudaEventRecord(ev_scan, 0);

    // side stream: scale s1h by dinv once scan is done (overlaps with scatter)
    cudaStreamWaitEvent(s2, ev_scan, 0);
    k_scale1<<<(N * 4 + 255) / 256, 256, 0, s2>>>(N);
    cudaEventRecord(ev_join, s2);

    k_scatter<<<(EQ + 255) / 256, 256>>>(ei, E);
    cudaStreamWaitEvent(0, ev_join, 0);

    // layer 1 aggregation, layer 2 gemm + aggregation
    k_agg1<<<(N + 7) / 8, 256>>>(b1, N);
    k_gemm2<<<(N + 63) / 64, 256>>>(W2, N);
    k_agg2<<<(N + 7) / 8, 256>>>(b2, N);

    // link decode
    k_decode<<<(EL * 8 + 255) / 256, 256>>>(eli, out, EL);

    cudaEventDestroy(ev_fork);
    cudaEventDestroy(ev_scan);
    cudaEventDestroy(ev_join);
    cudaStreamDestroy(s2);
}